// round 12
// baseline (speedup 1.0000x reference)
#include <cuda_runtime.h>
#include <cuda_bf16.h>
#include <math.h>
#include <stdint.h>

#define NTOK 131072
#define MMAX 132096   // NTOK + 8*128 padding

// ---------------- device scratch (static; no allocation) ----------------
__device__ float g_buf1[33816576];   // u (w1 out)
__device__ float g_buf2[33816576];   // ext (gate in) then relu(h7)
__device__ float g_z[16777216];      // NTOK x 128
__device__ __nv_bfloat16 g_peh[12582912], g_pel[12582912];   // NTOK x 96 posenc split
__device__ __nv_bfloat16 g_h0h[33554432], g_h0l[33554432];   // split h0
__device__ __nv_bfloat16 g_p1h[33816576], g_p1l[33816576];   // act ping
__device__ __nv_bfloat16 g_p2h[33816576], g_p2l[33816576];   // act pong
__device__ __nv_bfloat16 g_cath[50331648], g_catl[50331648]; // NTOK x 384
__device__ __nv_bfloat16 g_wxh[24576],  g_wxl[24576];        // w_xyz^T [256,96]
__device__ __nv_bfloat16 g_wg1h[65536], g_wg1l[65536];       // wg1^T
__device__ __nv_bfloat16 g_wg2h[65536], g_wg2l[65536];       // wg2^T
__device__ __nv_bfloat16 g_wah[1572864], g_wal[1572864];     // eW_a^T  24 x [256,256]
__device__ __nv_bfloat16 g_w3h[1048576], g_w3l[1048576];     // eW3^T    8 x [256,512]
__device__ __nv_bfloat16 g_wbh[1572864], g_wbl[1572864];     // eW_b^T
__device__ __nv_bfloat16 g_w1h[65536],  g_w1l[65536];        // w1^T
__device__ __nv_bfloat16 g_w2h[49152],  g_w2l[49152];        // w2^T [128,384]
__device__ float g_gate[NTOK];
__device__ int   g_eidx[NTOK], g_slot[NTOK], g_perm[MMAX];
__device__ int   g_hist[4096], g_base[4096], g_counts[8], g_off[9];
__device__ int   g_fcnt;
__device__ int   g_flist[NTOK];

// ---------------- helpers ----------------
__device__ __forceinline__ uint32_t smem_u32(const void* p) {
    uint32_t a;
    asm("{ .reg .u64 t; cvta.to.shared.u64 t, %1; cvt.u32.u64 %0, t; }" : "=r"(a) : "l"(p));
    return a;
}
__device__ __forceinline__ void ldsm4(uint32_t* r, uint32_t addr) {
    asm volatile("ldmatrix.sync.aligned.m8n8.x4.shared.b16 {%0,%1,%2,%3}, [%4];"
                 : "=r"(r[0]), "=r"(r[1]), "=r"(r[2]), "=r"(r[3]) : "r"(addr));
}
__device__ __forceinline__ void mma_bf16(float* c, const uint32_t* a, const uint32_t* b) {
    asm volatile("mma.sync.aligned.m16n8k16.row.col.f32.bf16.bf16.f32 "
                 "{%0,%1,%2,%3}, {%4,%5,%6,%7}, {%8,%9}, {%0,%1,%2,%3};"
                 : "+f"(c[0]), "+f"(c[1]), "+f"(c[2]), "+f"(c[3])
                 : "r"(a[0]), "r"(a[1]), "r"(a[2]), "r"(a[3]), "r"(b[0]), "r"(b[1]));
}
__device__ __forceinline__ void cpa16(uint32_t dst, const void* src) {
    asm volatile("cp.async.cg.shared.global [%0], [%1], 16;" :: "r"(dst), "l"(src));
}
#define CP_COMMIT() asm volatile("cp.async.commit_group;" ::: "memory")
#define CP_WAIT1()  asm volatile("cp.async.wait_group 1;" ::: "memory")
#define CP_WAIT0()  asm volatile("cp.async.wait_group 0;" ::: "memory")
__device__ __forceinline__ void split2(float v, __nv_bfloat16& h, __nv_bfloat16& l) {
    h = __float2bfloat16_rn(v);
    l = __float2bfloat16_rn(v - __bfloat162float(h));
}
__device__ __forceinline__ float pe_val(const float* xr, int k) {
    if (k < 3) return xr[k];
    int r = k - 3, f = r / 6, q = r % 6, d = q % 3, s = q / 3;
    double arg = (double)xr[d] * (double)(1 << f);
    return s ? (float)cos(arg) : (float)sin(arg);
}

// ---------------- small kernels ----------------
__global__ void k_reset() {
    int i = blockIdx.x * 256 + threadIdx.x;
    if (i < MMAX) g_perm[i] = 0;
    if (i == 0) g_fcnt = 0;
}

__global__ void k_pe(const float* __restrict__ x) {
    int idx = blockIdx.x * 256 + threadIdx.x;
    if (idx >= NTOK * 96) return;
    int t = idx / 96, k = idx - t * 96;
    float v = (k < 75) ? pe_val(x + t * 7, k) : 0.f;
    __nv_bfloat16 h, l; split2(v, h, l);
    g_peh[idx] = h; g_pel[idx] = l;
}

__global__ void k_wt(const float* __restrict__ src, __nv_bfloat16* __restrict__ dh,
                     __nv_bfloat16* __restrict__ dl, int K, int N, int Kpad,
                     long sstride, long dstride) {
    __shared__ float t[32][33];
    int b = blockIdx.z, k0 = blockIdx.x * 32, n0 = blockIdx.y * 32;
#pragma unroll
    for (int i = 0; i < 32; i += 8) {
        int k = k0 + threadIdx.y + i, n = n0 + threadIdx.x;
        t[threadIdx.y + i][threadIdx.x] = (k < K) ? src[b * sstride + (long)k * N + n] : 0.f;
    }
    __syncthreads();
#pragma unroll
    for (int i = 0; i < 32; i += 8) {
        int n = n0 + threadIdx.y + i, k = k0 + threadIdx.x;
        float v = t[threadIdx.x][threadIdx.y + i];
        __nv_bfloat16 h, l; split2(v, h, l);
        long o = b * dstride + (long)n * Kpad + k;
        dh[o] = h; dl[o] = l;
    }
}

__global__ void k_gate(const float* __restrict__ lng, const float* __restrict__ lnb,
                       const float* __restrict__ wg) {
    int t = blockIdx.x * 8 + (threadIdx.x >> 5);
    int lane = threadIdx.x & 31;
    const float* row = g_buf2 + (size_t)t * 256;
    float xv[8], s = 0.f;
#pragma unroll
    for (int i = 0; i < 8; i++) { xv[i] = row[lane + i * 32]; s += xv[i]; }
#pragma unroll
    for (int o = 16; o; o >>= 1) s += __shfl_xor_sync(0xffffffffu, s, o);
    float mean = s * (1.f / 256.f), vv = 0.f;
#pragma unroll
    for (int i = 0; i < 8; i++) { float d = xv[i] - mean; vv += d * d; }
#pragma unroll
    for (int o = 16; o; o >>= 1) vv += __shfl_xor_sync(0xffffffffu, vv, o);
    float rstd = rsqrtf(vv * (1.f / 256.f) + 1e-5f);
    float l[8] = {0,0,0,0,0,0,0,0};
#pragma unroll
    for (int i = 0; i < 8; i++) {
        int k = lane + i * 32;
        float ln = (xv[i] - mean) * rstd * lng[k] + lnb[k];
#pragma unroll
        for (int e = 0; e < 8; e++) l[e] = fmaf(ln, wg[k * 8 + e], l[e]);
    }
#pragma unroll
    for (int o = 16; o; o >>= 1)
#pragma unroll
        for (int e = 0; e < 8; e++) l[e] += __shfl_xor_sync(0xffffffffu, l[e], o);
    if (lane == 0) {
        float best = -1e30f, second = -1e30f; int bi = 0;
#pragma unroll
        for (int e = 0; e < 8; e++) {
            float v = l[e];
            if (v > best) { second = best; best = v; bi = e; }
            else if (v > second) second = v;
        }
        float se = 0.f;
#pragma unroll
        for (int e = 0; e < 8; e++) se += expf(l[e] - best);
        g_eidx[t] = bi; g_gate[t] = 1.f / se;
        if (best - second < 2e-3f) {
            int i = atomicAdd(&g_fcnt, 1);
            g_flist[i] = t;
        }
    }
}

__global__ void k_exact(const float* __restrict__ x,
                        const float* __restrict__ w_xyz, const float* __restrict__ b_xyz,
                        const float* __restrict__ wg1, const float* __restrict__ bg1,
                        const float* __restrict__ wg2, const float* __restrict__ bg2,
                        const float* __restrict__ lng, const float* __restrict__ lnb,
                        const float* __restrict__ wg) {
    __shared__ float pe[80], h0[256], f1[256], f2[256], ln[256], sred[256];
    int tid = threadIdx.x;
    for (int fi = blockIdx.x; fi < g_fcnt; fi += gridDim.x) {
        int t = g_flist[fi];
        if (tid < 75) pe[tid] = pe_val(x + t * 7, tid);
        __syncthreads();
        float a = b_xyz[tid];
        for (int k = 0; k < 75; k++) a = fmaf(pe[k], w_xyz[k * 256 + tid], a);
        h0[tid] = a;
        __syncthreads();
        a = bg1[tid];
        for (int k = 0; k < 256; k++) a = fmaf(h0[k], wg1[k * 256 + tid], a);
        f1[tid] = fmaxf(a, 0.f);
        __syncthreads();
        a = bg2[tid];
        for (int k = 0; k < 256; k++) a = fmaf(f1[k], wg2[k * 256 + tid], a);
        f2[tid] = a;
        sred[tid] = a;
        __syncthreads();
        for (int s = 128; s; s >>= 1) { if (tid < s) sred[tid] += sred[tid + s]; __syncthreads(); }
        float mean = sred[0] * (1.f / 256.f);
        __syncthreads();
        float d = f2[tid] - mean;
        sred[tid] = d * d;
        __syncthreads();
        for (int s = 128; s; s >>= 1) { if (tid < s) sred[tid] += sred[tid + s]; __syncthreads(); }
        float rstd = rsqrtf(sred[0] * (1.f / 256.f) + 1e-5f);
        __syncthreads();
        ln[tid] = (f2[tid] - mean) * rstd * lng[tid] + lnb[tid];
        __syncthreads();
        if (tid < 32) {
            int lane = tid;
            float l[8] = {0,0,0,0,0,0,0,0};
#pragma unroll
            for (int i = 0; i < 8; i++) {
                int k = lane + i * 32;
                float lv = ln[k];
#pragma unroll
                for (int e = 0; e < 8; e++) l[e] = fmaf(lv, wg[k * 8 + e], l[e]);
            }
#pragma unroll
            for (int o = 16; o; o >>= 1)
#pragma unroll
                for (int e = 0; e < 8; e++) l[e] += __shfl_xor_sync(0xffffffffu, l[e], o);
            if (lane == 0) {
                float best = l[0]; int bi = 0;
#pragma unroll
                for (int e = 1; e < 8; e++) if (l[e] > best) { best = l[e]; bi = e; }
                float se = 0.f;
#pragma unroll
                for (int e = 0; e < 8; e++) se += expf(l[e] - best);
                g_eidx[t] = bi; g_gate[t] = 1.f / se;
            }
        }
        __syncthreads();
    }
}

__global__ void k_hist() {
    __shared__ int h[8];
    if (threadIdx.x < 8) h[threadIdx.x] = 0;
    __syncthreads();
    atomicAdd(&h[g_eidx[blockIdx.x * 256 + threadIdx.x]], 1);
    __syncthreads();
    if (threadIdx.x < 8) g_hist[blockIdx.x * 8 + threadIdx.x] = h[threadIdx.x];
}

__global__ void k_scan(const int* __restrict__ cap) {
    int e = threadIdx.x;
    if (e < 8) {
        int run = 0;
        for (int b = 0; b < 512; b++) { g_base[b * 8 + e] = run; run += g_hist[b * 8 + e]; }
        g_counts[e] = run;
    }
    __syncthreads();
    if (threadIdx.x == 0) {
        int c = cap[0], o = 0;
        g_off[0] = 0;
        for (int q = 0; q < 8; q++) {
            int kc = g_counts[q]; if (kc > c) kc = c;
            o += ((kc + 127) >> 7) << 7;
            g_off[q + 1] = o;
        }
    }
}

__global__ void k_loc(const int* __restrict__ cap) {
    int b = blockIdx.x, e = threadIdx.x;
    if (e >= 8) return;
    int run = g_base[b * 8 + e], o = g_off[e], c = cap[0];
    for (int i = 0; i < 256; i++) {
        int t = b * 256 + i;
        if (g_eidx[t] == e) {
            if (run < c) { int s = o + run; g_perm[s] = t; g_slot[t] = s; }
            else g_slot[t] = -1;
            run++;
        }
    }
}

__global__ void k_cat(const float* __restrict__ x, const float* __restrict__ emb,
                      const float* __restrict__ b1) {
    int t = blockIdx.x, j = threadIdx.x;
    int s = g_slot[t];
    float gt = (s >= 0) ? g_gate[t] : 0.f;
    int ss = (s >= 0) ? s : 0;
    size_t base = (size_t)t * 384;
    const float* ub = g_buf1 + (size_t)ss * 256;
    __nv_bfloat16 h, l;
    float v0 = fmaf(gt, ub[j], b1[j]);
    split2(v0, h, l); g_cath[base + j] = h; g_catl[base + j] = l;
    float v1 = fmaf(gt, ub[128 + j], b1[128 + j]);
    split2(v1, h, l); g_cath[base + 128 + j] = h; g_catl[base + 128 + j] = l;
    if (j < 27) {
        float v;
        if (j < 3) v = x[t * 7 + 3 + j];
        else {
            int r = j - 3, f = r / 6, q = r % 6, d = q % 3, sg = q / 3;
            double arg = (double)x[t * 7 + 3 + d] * (double)(1 << f);
            v = sg ? (float)cos(arg) : (float)sin(arg);
        }
        split2(v, h, l); g_cath[base + 256 + j] = h; g_catl[base + 256 + j] = l;
    }
    if (j < 48) {
        int a = (int)x[t * 7 + 6];
        split2(emb[a * 48 + j], h, l);
        g_cath[base + 283 + j] = h; g_catl[base + 283 + j] = l;
    }
    if (j < 53) { g_cath[base + 331 + j] = __float2bfloat16(0.f); g_catl[base + 331 + j] = __float2bfloat16(0.f); }
}

__global__ void k_final(const float* __restrict__ wc, const float* __restrict__ bc,
                        const float* __restrict__ ws, const float* __restrict__ bs,
                        float* __restrict__ out) {
    int t = blockIdx.x * 8 + (threadIdx.x >> 5);
    int lane = threadIdx.x & 31;
    int s = g_slot[t];
    float gt = (s >= 0) ? g_gate[t] : 0.f;
    int ss = (s >= 0) ? s : 0;
    float a0 = 0, a1 = 0, a2 = 0, sv = 0;
    const float* zr = g_z + (size_t)t * 128;
#pragma unroll
    for (int i = 0; i < 4; i++) {
        int k = lane + i * 32;
        float zz = zr[k];
        a0 = fmaf(zz, wc[k * 3 + 0], a0);
        a1 = fmaf(zz, wc[k * 3 + 1], a1);
        a2 = fmaf(zz, wc[k * 3 + 2], a2);
    }
    const float* hr = g_buf2 + (size_t)ss * 256;   // relu(h7)
#pragma unroll
    for (int i = 0; i < 8; i++) {
        int k = lane + i * 32;
        sv = fmaf(fmaxf(hr[k], 0.f), ws[k], sv);
    }
#pragma unroll
    for (int o = 16; o; o >>= 1) {
        a0 += __shfl_xor_sync(0xffffffffu, a0, o);
        a1 += __shfl_xor_sync(0xffffffffu, a1, o);
        a2 += __shfl_xor_sync(0xffffffffu, a2, o);
        sv += __shfl_xor_sync(0xffffffffu, sv, o);
    }
    if (lane == 0) {
        float r0 = a0 + bc[0], r1 = a1 + bc[1], r2 = a2 + bc[2];
        out[t * 4 + 0] = 1.f / (1.f + expf(-r0));
        out[t * 4 + 1] = 1.f / (1.f + expf(-r1));
        out[t * 4 + 2] = 1.f / (1.f + expf(-r2));
        float sp = fmaf(gt, sv, bs[0]);
        out[t * 4 + 3] = fmaxf(sp, 0.f) + log1pf(expf(-fabsf(sp)));
    }
}

// ---------------- mma.sync bf16x3 GEMM, pipelined ----------------
// BN=256: 512 thr, 16 warps (4x4 of 32x64), 3-stage, 1 sync/chunk, grid.y=1.
// BN=128: 256 thr, 8 warps (4x2), 2-stage (w2 only).
// stage layout: [Ah 10240 | Al 10240 | Bh BN*80 | Bl BN*80]
template<int AMODE, int EXPERT, int SLOTM, int RELU, int WF32, int WSPLIT, int HASBIAS, int BN>
__global__ void __launch_bounds__(2 * BN, 256 / BN)
mma_gemm(const __nv_bfloat16* __restrict__ Ah, const __nv_bfloat16* __restrict__ Al,
         const __nv_bfloat16* __restrict__ A2h, const __nv_bfloat16* __restrict__ A2l,
         const __nv_bfloat16* __restrict__ Wh, const __nv_bfloat16* __restrict__ Wl,
         const float* __restrict__ bias,
         float* __restrict__ outf, __nv_bfloat16* __restrict__ oh, __nv_bfloat16* __restrict__ ol,
         int lda, int Kfull, int KCH, int ldc, long wstride, int bstride,
         const int* __restrict__ perm, const int* __restrict__ off) {
    constexpr int NST = (BN == 128) ? 2 : 3;
    constexpr int T = 2 * BN;
    constexpr int BBUFB = BN * 80;
    constexpr int STAGE = 2 * 10240 + 2 * BBUFB;
    extern __shared__ __align__(16) __nv_bfloat16 dsm[];
    __shared__ int sperm[128];

    const int m0 = blockIdx.x * 128, n0 = blockIdx.y * BN;
    int e = 0;
    if (SLOTM) {
        if (m0 >= off[8]) return;
        if (EXPERT) {
#pragma unroll
            for (int q = 0; q < 7; q++) if (m0 >= off[q + 1]) e = q + 1;
        }
    }
    const int tid = threadIdx.x, lane = tid & 31, wid = tid >> 5;
    const int wm = (wid & 3) * 32, wn = (wid >> 2) * 64;

    if (AMODE >= 1 && tid < 128) sperm[tid] = perm[m0 + tid];
    if (AMODE >= 1) __syncthreads();

    const __nv_bfloat16* wph = Wh + (EXPERT ? (long)e * wstride : 0);
    const __nv_bfloat16* wpl = Wl + (EXPERT ? (long)e * wstride : 0);

    const uint32_t sb = smem_u32(dsm);
    const int a_r = lane & 15, a_c = (lane & 16) >> 1;
    const int b_r = ((lane >> 4) << 3) + (lane & 7), b_c = lane & 8;

    auto issue = [&](int kc, int st) {
        uint32_t base = sb + st * STAGE;
        // A: 128 rows x 4 segs = 512 units
#pragma unroll
        for (int i = 0; i < (512 + T - 1) / T; i++) {
            int u = tid + i * T;
            int row = u >> 2, seg = u & 3;
            const __nv_bfloat16 *ph, *pl;
            if (AMODE == 2) {
                if (kc < 8) {
                    long r = sperm[row];
                    ph = Ah + r * 256 + kc * 32 + seg * 8;
                    pl = Al + r * 256 + kc * 32 + seg * 8;
                } else {
                    long r = m0 + row;
                    ph = A2h + r * 256 + (kc - 8) * 32 + seg * 8;
                    pl = A2l + r * 256 + (kc - 8) * 32 + seg * 8;
                }
            } else {
                long r = (AMODE == 1) ? sperm[row] : (m0 + row);
                ph = Ah + r * lda + kc * 32 + seg * 8;
                pl = Al + r * lda + kc * 32 + seg * 8;
            }
            uint32_t so = row * 80 + seg * 16;
            cpa16(base + so, ph);
            cpa16(base + 10240 + so, pl);
        }
        // B: BN rows x 4 segs
#pragma unroll
        for (int i = 0; i < 2; i++) {
            int u = tid + i * T;
            int row = u >> 2, seg = u & 3;
            const __nv_bfloat16* qh = wph + (long)(n0 + row) * Kfull + kc * 32 + seg * 8;
            const __nv_bfloat16* ql = wpl + (long)(n0 + row) * Kfull + kc * 32 + seg * 8;
            uint32_t so = row * 80 + seg * 16;
            cpa16(base + 20480 + so, qh);
            cpa16(base + 20480 + BBUFB + so, ql);
        }
    };

    float c[2][8][4];
#pragma unroll
    for (int i = 0; i < 2; i++)
#pragma unroll
        for (int j = 0; j < 8; j++)
#pragma unroll
            for (int q = 0; q < 4; q++) c[i][j][q] = 0.f;

    auto compute = [&](int st) {
        uint32_t bA_h = sb + st * STAGE;
        uint32_t bA_l = bA_h + 10240;
        uint32_t bB_h = bA_h + 20480;
        uint32_t bB_l = bB_h + BBUFB;
#pragma unroll
        for (int kt = 0; kt < 2; kt++) {
            uint32_t ahf[2][4], alf[2][4];
#pragma unroll
            for (int mt = 0; mt < 2; mt++) {
                uint32_t offa = ((wm + mt * 16 + a_r) * 40 + kt * 16 + a_c) * 2;
                ldsm4(ahf[mt], bA_h + offa);
                ldsm4(alf[mt], bA_l + offa);
            }
#pragma unroll
            for (int ng = 0; ng < 4; ng++) {
                uint32_t bh[4], bl[4];
                uint32_t offb = ((wn + ng * 16 + b_r) * 40 + kt * 16 + b_c) * 2;
                ldsm4(bh, bB_h + offb);
                ldsm4(bl, bB_l + offb);
#pragma unroll
                for (int mt = 0; mt < 2; mt++)
#pragma unroll
                    for (int ns = 0; ns < 2; ns++) {
                        float* cc = c[mt][ng * 2 + ns];
                        mma_bf16(cc, ahf[mt], bh + ns * 2);
                        mma_bf16(cc, ahf[mt], bl + ns * 2);
                        mma_bf16(cc, alf[mt], bh + ns * 2);
                    }
            }
        }
    };

    if (NST == 2) {
        issue(0, 0); CP_COMMIT();
        for (int kc = 0; kc < KCH; kc++) {
            int cs = kc & 1;
            if (kc + 1 < KCH) { issue(kc + 1, cs ^ 1); CP_COMMIT(); CP_WAIT1(); }
            else CP_WAIT0();
            __syncthreads();
            compute(cs);
            __syncthreads();
        }
    } else {
        issue(0, 0); CP_COMMIT();
        issue(1, 1); CP_COMMIT();
        for (int kc = 0; kc < KCH; kc++) {
            if (kc >= KCH - 1) CP_WAIT0(); else CP_WAIT1();
            __syncthreads();
            compute(kc % 3);
            if (kc + 2 < KCH) { issue(kc + 2, (kc + 2) % 3); CP_COMMIT(); }
        }
    }

#pragma unroll
    for (int mt = 0; mt < 2; mt++)
#pragma unroll
        for (int nt = 0; nt < 8; nt++) {
            int col = n0 + wn + nt * 8 + (lane & 3) * 2;
            float bv0 = 0.f, bv1 = 0.f;
            if (HASBIAS) {
                const float* bp = bias + (EXPERT ? e * bstride : 0) + col;
                bv0 = bp[0]; bv1 = bp[1];
            }
#pragma unroll
            for (int half = 0; half < 2; half++) {
                long row = m0 + wm + mt * 16 + (lane >> 2) + half * 8;
                float v0 = c[mt][nt][half * 2 + 0] + bv0;
                float v1 = c[mt][nt][half * 2 + 1] + bv1;
                if (RELU) { v0 = fmaxf(v0, 0.f); v1 = fmaxf(v1, 0.f); }
                if (WF32) {
                    outf[row * ldc + col] = v0;
                    outf[row * ldc + col + 1] = v1;
                }
                if (WSPLIT) {
                    __nv_bfloat16 h0_, l0_, h1_, l1_;
                    split2(v0, h0_, l0_); split2(v1, h1_, l1_);
                    oh[row * 256 + col] = h0_;     ol[row * 256 + col] = l0_;
                    oh[row * 256 + col + 1] = h1_; ol[row * 256 + col + 1] = l1_;
                }
            }
        }
}

// ---------------- launch ----------------
extern "C" void kernel_launch(void* const* d_in, const int* in_sizes, int n_in,
                              void* d_out, int out_size) {
    (void)in_sizes; (void)n_in; (void)out_size;
    const float* x     = (const float*)d_in[0];
    const float* emb_a = (const float*)d_in[1];
    const float* w_xyz = (const float*)d_in[2];
    const float* b_xyz = (const float*)d_in[3];
    const float* wg1   = (const float*)d_in[4];
    const float* bg1   = (const float*)d_in[5];
    const float* wg2   = (const float*)d_in[6];
    const float* bg2   = (const float*)d_in[7];
    const float* ln_g  = (const float*)d_in[8];
    const float* ln_b  = (const float*)d_in[9];
    const float* wg    = (const float*)d_in[10];
    const float* eW_a  = (const float*)d_in[11];
    const float* eb_a  = (const float*)d_in[12];
    const float* eW3   = (const float*)d_in[13];
    const float* eb3   = (const float*)d_in[14];
    const float* eW_b  = (const float*)d_in[15];
    const float* eb_b  = (const float*)d_in[16];
    const float* w1    = (const float*)d_in[17];
    const float* b1    = (const float*)d_in[18];
    const float* w2    = (const float*)d_in[19];
    const float* b2    = (const float*)d_in[20];
    const float* ws    = (const float*)d_in[21];
    const float* bs    = (const float*)d_in[22];
    const float* wc    = (const float*)d_in[23];
    const float* bc    = (const float*)d_in[24];
    const int*   cap   = (const int*)d_in[25];
    float* out = (float*)d_out;

    float *b1f, *b2f, *z;
    __nv_bfloat16 *peh, *pel, *h0h, *h0l, *p1h, *p1l, *p2h, *p2l, *cath, *catl;
    __nv_bfloat16 *wxh, *wxl, *wg1h, *wg1l, *wg2h, *wg2l;
    __nv_bfloat16 *wah, *wal, *w3h, *w3l, *wbh, *wbl, *w1h, *w1l, *w2h, *w2l;
    int *perm, *off;
    cudaGetSymbolAddress((void**)&b1f, g_buf1);  cudaGetSymbolAddress((void**)&b2f, g_buf2);
    cudaGetSymbolAddress((void**)&z, g_z);
    cudaGetSymbolAddress((void**)&peh, g_peh);   cudaGetSymbolAddress((void**)&pel, g_pel);
    cudaGetSymbolAddress((void**)&h0h, g_h0h);   cudaGetSymbolAddress((void**)&h0l, g_h0l);
    cudaGetSymbolAddress((void**)&p1h, g_p1h);   cudaGetSymbolAddress((void**)&p1l, g_p1l);
    cudaGetSymbolAddress((void**)&p2h, g_p2h);   cudaGetSymbolAddress((void**)&p2l, g_p2l);
    cudaGetSymbolAddress((void**)&cath, g_cath); cudaGetSymbolAddress((void**)&catl, g_catl);
    cudaGetSymbolAddress((void**)&wxh, g_wxh);   cudaGetSymbolAddress((void**)&wxl, g_wxl);
    cudaGetSymbolAddress((void**)&wg1h, g_wg1h); cudaGetSymbolAddress((void**)&wg1l, g_wg1l);
    cudaGetSymbolAddress((void**)&wg2h, g_wg2h); cudaGetSymbolAddress((void**)&wg2l, g_wg2l);
    cudaGetSymbolAddress((void**)&wah, g_wah);   cudaGetSymbolAddress((void**)&wal, g_wal);
    cudaGetSymbolAddress((void**)&w3h, g_w3h);   cudaGetSymbolAddress((void**)&w3l, g_w3l);
    cudaGetSymbolAddress((void**)&wbh, g_wbh);   cudaGetSymbolAddress((void**)&wbl, g_wbl);
    cudaGetSymbolAddress((void**)&w1h, g_w1h);   cudaGetSymbolAddress((void**)&w1l, g_w1l);
    cudaGetSymbolAddress((void**)&w2h, g_w2h);   cudaGetSymbolAddress((void**)&w2l, g_w2l);
    cudaGetSymbolAddress((void**)&perm, g_perm); cudaGetSymbolAddress((void**)&off, g_off);

    const int SM256 = 3 * (2 * 10240 + 2 * 256 * 80);   // 184320
    const int SM128 = 2 * (2 * 10240 + 2 * 128 * 80);   // 81920
    cudaFuncSetAttribute((const void*)mma_gemm<0,0,0,0,0,1,1,256>, cudaFuncAttributeMaxDynamicSharedMemorySize, SM256);
    cudaFuncSetAttribute((const void*)mma_gemm<0,0,0,1,0,1,1,256>, cudaFuncAttributeMaxDynamicSharedMemorySize, SM256);
    cudaFuncSetAttribute((const void*)mma_gemm<0,0,0,0,1,0,1,256>, cudaFuncAttributeMaxDynamicSharedMemorySize, SM256);
    cudaFuncSetAttribute((const void*)mma_gemm<1,1,1,1,0,1,1,256>, cudaFuncAttributeMaxDynamicSharedMemorySize, SM256);
    cudaFuncSetAttribute((const void*)mma_gemm<0,1,1,1,0,1,1,256>, cudaFuncAttributeMaxDynamicSharedMemorySize, SM256);
    cudaFuncSetAttribute((const void*)mma_gemm<2,1,1,1,0,1,1,256>, cudaFuncAttributeMaxDynamicSharedMemorySize, SM256);
    cudaFuncSetAttribute((const void*)mma_gemm<0,1,1,1,1,1,1,256>, cudaFuncAttributeMaxDynamicSharedMemorySize, SM256);
    cudaFuncSetAttribute((const void*)mma_gemm<0,0,1,0,1,0,0,256>, cudaFuncAttributeMaxDynamicSharedMemorySize, SM256);
    cudaFuncSetAttribute((const void*)mma_gemm<0,0,0,1,1,0,1,128>, cudaFuncAttributeMaxDynamicSharedMemorySize, SM128);

    k_reset<<<MMAX / 256, 256>>>();
    k_pe<<<(NTOK * 96 + 255) / 256, 256>>>(x);

    // weight transposes + bf16 splits
    k_wt<<<dim3(3, 8, 1),  dim3(32, 8)>>>(w_xyz, wxh, wxl, 75, 256, 96, 19200, 24576);
    k_wt<<<dim3(8, 8, 1),  dim3(32, 8)>>>(wg1, wg1h, wg1l, 256, 256, 256, 65536, 65536);
    k_wt<<<dim3(8, 8, 1),  dim3(32, 8)>>>(wg2, wg2h, wg2l, 256, 256, 256, 65536, 65536);
    k_wt<<<dim3(8, 8, 24), dim3(32, 8)>>>(eW_a, wah, wal, 256, 256, 256, 65536, 65536);
    k_wt<<<dim3(16, 8, 8), dim3(32, 8)>>>(eW3, w3h, w3l, 512, 256, 512, 131072, 131072);
    k_wt<<<dim3(8, 8, 24), dim3(32, 8)>>>(eW_b, wbh, wbl, 256, 256, 256, 65536, 65536);
    k_wt<<<dim3(8, 8, 1),  dim3(32, 8)>>>(w1, w1h, w1l, 256, 256, 256, 65536, 65536);
    k_wt<<<dim3(12, 4, 1), dim3(32, 8)>>>(w2, w2h, w2l, 331, 128, 384, 42368, 49152);

    // backbone (bf16x3; argmax protected by margin-gated exact recompute)
    dim3 gT(NTOK / 128, 1);
    mma_gemm<0,0,0,0,0,1,1,256><<<gT, 512, SM256>>>(peh, pel, nullptr, nullptr, wxh, wxl, b_xyz,
        nullptr, h0h, h0l, 96, 96, 3, 256, 0, 0, nullptr, nullptr);
    mma_gemm<0,0,0,1,0,1,1,256><<<gT, 512, SM256>>>(h0h, h0l, nullptr, nullptr, wg1h, wg1l, bg1,
        nullptr, p1h, p1l, 256, 256, 8, 256, 0, 0, nullptr, nullptr);
    mma_gemm<0,0,0,0,1,0,1,256><<<gT, 512, SM256>>>(p1h, p1l, nullptr, nullptr, wg2h, wg2l, bg2,
        b2f, nullptr, nullptr, 256, 256, 8, 256, 0, 0, nullptr, nullptr);

    // routing
    k_gate<<<NTOK / 8, 256>>>(ln_g, ln_b, wg);
    k_exact<<<256, 256>>>(x, w_xyz, b_xyz, wg1, bg1, wg2, bg2, ln_g, ln_b, wg);
    k_hist<<<512, 256>>>();
    k_scan<<<1, 32>>>(cap);
    k_loc<<<512, 32>>>(cap);

    // expert chain
    dim3 gS(MMAX / 128, 1);
    mma_gemm<1,1,1,1,0,1,1,256><<<gS, 512, SM256>>>(h0h, h0l, nullptr, nullptr, wah, wal, eb_a,
        nullptr, p1h, p1l, 256, 256, 8, 256, 196608, 768, perm, off);
    mma_gemm<0,1,1,1,0,1,1,256><<<gS, 512, SM256>>>(p1h, p1l, nullptr, nullptr, wah + 65536, wal + 65536, eb_a + 256,
        nullptr, p2h, p2l, 256, 256, 8, 256, 196608, 768, perm, off);
    mma_gemm<0,1,1,1,0,1,1,256><<<gS, 512, SM256>>>(p2h, p2l, nullptr, nullptr, wah + 131072, wal + 131072, eb_a + 512,
        nullptr, p1h, p1l, 256, 256, 8, 256, 196608, 768, perm, off);
    mma_gemm<2,1,1,1,0,1,1,256><<<gS, 512, SM256>>>(h0h, h0l, p1h, p1l, w3h, w3l, eb3,
        nullptr, p2h, p2l, 256, 512, 16, 256, 131072, 256, perm, off);
    mma_gemm<0,1,1,1,0,1,1,256><<<gS, 512, SM256>>>(p2h, p2l, nullptr, nullptr, wbh, wbl, eb_b,
        nullptr, p1h, p1l, 256, 256, 8, 256, 196608, 768, perm, off);
    mma_gemm<0,1,1,1,0,1,1,256><<<gS, 512, SM256>>>(p1h, p1l, nullptr, nullptr, wbh + 65536, wbl + 65536, eb_b + 256,
        nullptr, p2h, p2l, 256, 256, 8, 256, 196608, 768, perm, off);
    mma_gemm<0,1,1,1,1,1,1,256><<<gS, 512, SM256>>>(p2h, p2l, nullptr, nullptr, wbh + 131072, wbl + 131072, eb_b + 512,
        b2f, p1h, p1l, 256, 256, 8, 256, 196608, 768, perm, off);
    mma_gemm<0,0,1,0,1,0,0,256><<<gS, 512, SM256>>>(p1h, p1l, nullptr, nullptr, w1h, w1l, nullptr,
        b1f, nullptr, nullptr, 256, 256, 8, 256, 0, 0, perm, off);

    // heads
    k_cat<<<NTOK, 128>>>(x, emb_a, b1);
    mma_gemm<0,0,0,1,1,0,1,128><<<dim3(NTOK / 128, 1), 256, SM128>>>(cath, catl, nullptr, nullptr, w2h, w2l, b2,
        z, nullptr, nullptr, 384, 384, 12, 128, 0, 0, perm, off);
    k_final<<<NTOK / 8, 256>>>(wc, bc, ws, bs, out);
}

// round 13
// speedup vs baseline: 1.0060x; 1.0060x over previous
#include <cuda_runtime.h>
#include <cuda_bf16.h>
#include <math.h>
#include <stdint.h>

#define NTOK 131072
#define MMAX 132096   // NTOK + 8*128 padding

// ---------------- device scratch (static; no allocation) ----------------
__device__ float g_buf1[33816576];   // u (w1 out)
__device__ float g_buf2[33816576];   // ext (gate in) then relu(h7)
__device__ float g_z[16777216];      // NTOK x 128
__device__ __nv_bfloat16 g_peh[12582912], g_pel[12582912];   // NTOK x 96 posenc split
__device__ __nv_bfloat16 g_h0h[33554432], g_h0l[33554432];   // split h0
__device__ __nv_bfloat16 g_p1h[33816576], g_p1l[33816576];   // act ping
__device__ __nv_bfloat16 g_p2h[33816576], g_p2l[33816576];   // act pong
__device__ __nv_bfloat16 g_cath[50331648], g_catl[50331648]; // NTOK x 384
__device__ __nv_bfloat16 g_wxh[24576],  g_wxl[24576];        // w_xyz^T [256,96]
__device__ __nv_bfloat16 g_wg1h[65536], g_wg1l[65536];       // wg1^T
__device__ __nv_bfloat16 g_wg2h[65536], g_wg2l[65536];       // wg2^T
__device__ __nv_bfloat16 g_wah[1572864], g_wal[1572864];     // eW_a^T  24 x [256,256]
__device__ __nv_bfloat16 g_w3h[1048576], g_w3l[1048576];     // eW3^T    8 x [256,512]
__device__ __nv_bfloat16 g_wbh[1572864], g_wbl[1572864];     // eW_b^T
__device__ __nv_bfloat16 g_w1h[65536],  g_w1l[65536];        // w1^T
__device__ __nv_bfloat16 g_w2h[49152],  g_w2l[49152];        // w2^T [128,384]
__device__ float g_gate[NTOK];
__device__ int   g_eidx[NTOK], g_slot[NTOK], g_perm[MMAX];
__device__ int   g_hist[4096], g_base[4096], g_counts[8], g_off[9];
__device__ int   g_fcnt;
__device__ int   g_flist[NTOK];

// ---------------- helpers ----------------
__device__ __forceinline__ uint32_t smem_u32(const void* p) {
    uint32_t a;
    asm("{ .reg .u64 t; cvta.to.shared.u64 t, %1; cvt.u32.u64 %0, t; }" : "=r"(a) : "l"(p));
    return a;
}
__device__ __forceinline__ void ldsm4(uint32_t* r, uint32_t addr) {
    asm volatile("ldmatrix.sync.aligned.m8n8.x4.shared.b16 {%0,%1,%2,%3}, [%4];"
                 : "=r"(r[0]), "=r"(r[1]), "=r"(r[2]), "=r"(r[3]) : "r"(addr));
}
__device__ __forceinline__ void mma_bf16(float* c, const uint32_t* a, const uint32_t* b) {
    asm volatile("mma.sync.aligned.m16n8k16.row.col.f32.bf16.bf16.f32 "
                 "{%0,%1,%2,%3}, {%4,%5,%6,%7}, {%8,%9}, {%0,%1,%2,%3};"
                 : "+f"(c[0]), "+f"(c[1]), "+f"(c[2]), "+f"(c[3])
                 : "r"(a[0]), "r"(a[1]), "r"(a[2]), "r"(a[3]), "r"(b[0]), "r"(b[1]));
}
__device__ __forceinline__ void cpa16(uint32_t dst, const void* src) {
    asm volatile("cp.async.cg.shared.global [%0], [%1], 16;" :: "r"(dst), "l"(src));
}
#define CP_COMMIT() asm volatile("cp.async.commit_group;" ::: "memory")
#define CP_WAIT1()  asm volatile("cp.async.wait_group 1;" ::: "memory")
#define CP_WAIT0()  asm volatile("cp.async.wait_group 0;" ::: "memory")
__device__ __forceinline__ void split2(float v, __nv_bfloat16& h, __nv_bfloat16& l) {
    h = __float2bfloat16_rn(v);
    l = __float2bfloat16_rn(v - __bfloat162float(h));
}
__device__ __forceinline__ float pe_val(const float* xr, int k) {
    // fp32 path: x*2^f is exact (power-of-2 scale); sinf/cosf are 1-2 ulp here.
    if (k < 3) return xr[k];
    int r = k - 3, f = r / 6, q = r % 6, d = q % 3, s = q / 3;
    float arg = xr[d] * (float)(1 << f);
    return s ? cosf(arg) : sinf(arg);
}

// ---------------- small kernels ----------------
__global__ void k_reset() {
    int i = blockIdx.x * 256 + threadIdx.x;
    if (i < MMAX) g_perm[i] = 0;
    if (i == 0) g_fcnt = 0;
}

// posenc(xyz,12) -> bf16 hi/lo [NTOK,96]; thread-per-(freq,dim) pair via sincosf
__global__ void k_pe(const float* __restrict__ x) {
    int idx = blockIdx.x * 256 + threadIdx.x;
    if (idx >= NTOK * 40) return;
    int t = idx / 40, r = idx - t * 40;
    size_t base = (size_t)t * 96;
    __nv_bfloat16 h, l;
    if (r < 3) {
        split2(x[t * 7 + r], h, l);
        g_peh[base + r] = h; g_pel[base + r] = l;
    } else if (r < 39) {
        int p = r - 3, f = p / 3, d = p % 3;
        float s, c;
        sincosf(x[t * 7 + d] * (float)(1 << f), &s, &c);
        int ks = 3 + f * 6 + d, kc = ks + 3;
        split2(s, h, l); g_peh[base + ks] = h; g_pel[base + ks] = l;
        split2(c, h, l); g_peh[base + kc] = h; g_pel[base + kc] = l;
    } else {
        __nv_bfloat16 z = __float2bfloat16(0.f);
        for (int c = 75; c < 96; c++) { g_peh[base + c] = z; g_pel[base + c] = z; }
    }
}

__global__ void k_wt(const float* __restrict__ src, __nv_bfloat16* __restrict__ dh,
                     __nv_bfloat16* __restrict__ dl, int K, int N, int Kpad,
                     long sstride, long dstride) {
    __shared__ float t[32][33];
    int b = blockIdx.z, k0 = blockIdx.x * 32, n0 = blockIdx.y * 32;
#pragma unroll
    for (int i = 0; i < 32; i += 8) {
        int k = k0 + threadIdx.y + i, n = n0 + threadIdx.x;
        t[threadIdx.y + i][threadIdx.x] = (k < K) ? src[b * sstride + (long)k * N + n] : 0.f;
    }
    __syncthreads();
#pragma unroll
    for (int i = 0; i < 32; i += 8) {
        int n = n0 + threadIdx.y + i, k = k0 + threadIdx.x;
        float v = t[threadIdx.x][threadIdx.y + i];
        __nv_bfloat16 h, l; split2(v, h, l);
        long o = b * dstride + (long)n * Kpad + k;
        dh[o] = h; dl[o] = l;
    }
}

__global__ void k_gate(const float* __restrict__ lng, const float* __restrict__ lnb,
                       const float* __restrict__ wg) {
    int t = blockIdx.x * 8 + (threadIdx.x >> 5);
    int lane = threadIdx.x & 31;
    const float* row = g_buf2 + (size_t)t * 256;
    float xv[8], s = 0.f;
#pragma unroll
    for (int i = 0; i < 8; i++) { xv[i] = row[lane + i * 32]; s += xv[i]; }
#pragma unroll
    for (int o = 16; o; o >>= 1) s += __shfl_xor_sync(0xffffffffu, s, o);
    float mean = s * (1.f / 256.f), vv = 0.f;
#pragma unroll
    for (int i = 0; i < 8; i++) { float d = xv[i] - mean; vv += d * d; }
#pragma unroll
    for (int o = 16; o; o >>= 1) vv += __shfl_xor_sync(0xffffffffu, vv, o);
    float rstd = rsqrtf(vv * (1.f / 256.f) + 1e-5f);
    float l[8] = {0,0,0,0,0,0,0,0};
#pragma unroll
    for (int i = 0; i < 8; i++) {
        int k = lane + i * 32;
        float ln = (xv[i] - mean) * rstd * lng[k] + lnb[k];
#pragma unroll
        for (int e = 0; e < 8; e++) l[e] = fmaf(ln, wg[k * 8 + e], l[e]);
    }
#pragma unroll
    for (int o = 16; o; o >>= 1)
#pragma unroll
        for (int e = 0; e < 8; e++) l[e] += __shfl_xor_sync(0xffffffffu, l[e], o);
    if (lane == 0) {
        float best = -1e30f, second = -1e30f; int bi = 0;
#pragma unroll
        for (int e = 0; e < 8; e++) {
            float v = l[e];
            if (v > best) { second = best; best = v; bi = e; }
            else if (v > second) second = v;
        }
        float se = 0.f;
#pragma unroll
        for (int e = 0; e < 8; e++) se += expf(l[e] - best);
        g_eidx[t] = bi; g_gate[t] = 1.f / se;
        if (best - second < 2e-3f) {
            int i = atomicAdd(&g_fcnt, 1);
            g_flist[i] = t;
        }
    }
}

__global__ void k_exact(const float* __restrict__ x,
                        const float* __restrict__ w_xyz, const float* __restrict__ b_xyz,
                        const float* __restrict__ wg1, const float* __restrict__ bg1,
                        const float* __restrict__ wg2, const float* __restrict__ bg2,
                        const float* __restrict__ lng, const float* __restrict__ lnb,
                        const float* __restrict__ wg) {
    __shared__ float pe[80], h0[256], f1[256], f2[256], ln[256], sred[256];
    int tid = threadIdx.x;
    for (int fi = blockIdx.x; fi < g_fcnt; fi += gridDim.x) {
        int t = g_flist[fi];
        if (tid < 75) pe[tid] = pe_val(x + t * 7, tid);
        __syncthreads();
        float a = b_xyz[tid];
        for (int k = 0; k < 75; k++) a = fmaf(pe[k], w_xyz[k * 256 + tid], a);
        h0[tid] = a;
        __syncthreads();
        a = bg1[tid];
        for (int k = 0; k < 256; k++) a = fmaf(h0[k], wg1[k * 256 + tid], a);
        f1[tid] = fmaxf(a, 0.f);
        __syncthreads();
        a = bg2[tid];
        for (int k = 0; k < 256; k++) a = fmaf(f1[k], wg2[k * 256 + tid], a);
        f2[tid] = a;
        sred[tid] = a;
        __syncthreads();
        for (int s = 128; s; s >>= 1) { if (tid < s) sred[tid] += sred[tid + s]; __syncthreads(); }
        float mean = sred[0] * (1.f / 256.f);
        __syncthreads();
        float d = f2[tid] - mean;
        sred[tid] = d * d;
        __syncthreads();
        for (int s = 128; s; s >>= 1) { if (tid < s) sred[tid] += sred[tid + s]; __syncthreads(); }
        float rstd = rsqrtf(sred[0] * (1.f / 256.f) + 1e-5f);
        __syncthreads();
        ln[tid] = (f2[tid] - mean) * rstd * lng[tid] + lnb[tid];
        __syncthreads();
        if (tid < 32) {
            int lane = tid;
            float l[8] = {0,0,0,0,0,0,0,0};
#pragma unroll
            for (int i = 0; i < 8; i++) {
                int k = lane + i * 32;
                float lv = ln[k];
#pragma unroll
                for (int e = 0; e < 8; e++) l[e] = fmaf(lv, wg[k * 8 + e], l[e]);
            }
#pragma unroll
            for (int o = 16; o; o >>= 1)
#pragma unroll
                for (int e = 0; e < 8; e++) l[e] += __shfl_xor_sync(0xffffffffu, l[e], o);
            if (lane == 0) {
                float best = l[0]; int bi = 0;
#pragma unroll
                for (int e = 1; e < 8; e++) if (l[e] > best) { best = l[e]; bi = e; }
                float se = 0.f;
#pragma unroll
                for (int e = 0; e < 8; e++) se += expf(l[e] - best);
                g_eidx[t] = bi; g_gate[t] = 1.f / se;
            }
        }
        __syncthreads();
    }
}

__global__ void k_hist() {
    __shared__ int h[8];
    if (threadIdx.x < 8) h[threadIdx.x] = 0;
    __syncthreads();
    atomicAdd(&h[g_eidx[blockIdx.x * 256 + threadIdx.x]], 1);
    __syncthreads();
    if (threadIdx.x < 8) g_hist[blockIdx.x * 8 + threadIdx.x] = h[threadIdx.x];
}

__global__ void k_scan(const int* __restrict__ cap) {
    int e = threadIdx.x;
    if (e < 8) {
        int run = 0;
        for (int b = 0; b < 512; b++) { g_base[b * 8 + e] = run; run += g_hist[b * 8 + e]; }
        g_counts[e] = run;
    }
    __syncthreads();
    if (threadIdx.x == 0) {
        int c = cap[0], o = 0;
        g_off[0] = 0;
        for (int q = 0; q < 8; q++) {
            int kc = g_counts[q]; if (kc > c) kc = c;
            o += ((kc + 127) >> 7) << 7;
            g_off[q + 1] = o;
        }
    }
}

__global__ void k_loc(const int* __restrict__ cap) {
    int b = blockIdx.x, e = threadIdx.x;
    if (e >= 8) return;
    int run = g_base[b * 8 + e], o = g_off[e], c = cap[0];
    for (int i = 0; i < 256; i++) {
        int t = b * 256 + i;
        if (g_eidx[t] == e) {
            if (run < c) { int s = o + run; g_perm[s] = t; g_slot[t] = s; }
            else g_slot[t] = -1;
            run++;
        }
    }
}

// cat row -> bf16 hi/lo [NTOK,384]: [gate*u+b1 (256) | direnc(27) | aemb(48) | 0-pad(53)]
__global__ void k_cat(const float* __restrict__ x, const float* __restrict__ emb,
                      const float* __restrict__ b1) {
    int t = blockIdx.x, j = threadIdx.x;
    int s = g_slot[t];
    float gt = (s >= 0) ? g_gate[t] : 0.f;
    int ss = (s >= 0) ? s : 0;
    size_t base = (size_t)t * 384;
    const float* ub = g_buf1 + (size_t)ss * 256;
    __nv_bfloat16 h, l;
    float v0 = fmaf(gt, ub[j], b1[j]);
    split2(v0, h, l); g_cath[base + j] = h; g_catl[base + j] = l;
    float v1 = fmaf(gt, ub[128 + j], b1[128 + j]);
    split2(v1, h, l); g_cath[base + 128 + j] = h; g_catl[base + 128 + j] = l;
    if (j < 3) {
        split2(x[t * 7 + 3 + j], h, l);
        g_cath[base + 256 + j] = h; g_catl[base + 256 + j] = l;
    } else if (j < 15) {
        int p = j - 3, f = p / 3, d = p % 3;
        float sv, cv;
        sincosf(x[t * 7 + 3 + d] * (float)(1 << f), &sv, &cv);
        int ks = 256 + 3 + f * 6 + d, kc = ks + 3;
        split2(sv, h, l); g_cath[base + ks] = h; g_catl[base + ks] = l;
        split2(cv, h, l); g_cath[base + kc] = h; g_catl[base + kc] = l;
    }
    if (j < 48) {
        int a = (int)x[t * 7 + 6];
        split2(emb[a * 48 + j], h, l);
        g_cath[base + 283 + j] = h; g_catl[base + 283 + j] = l;
    }
    if (j < 53) { g_cath[base + 331 + j] = __float2bfloat16(0.f); g_catl[base + 331 + j] = __float2bfloat16(0.f); }
}

__global__ void k_final(const float* __restrict__ wc, const float* __restrict__ bc,
                        const float* __restrict__ ws, const float* __restrict__ bs,
                        float* __restrict__ out) {
    int t = blockIdx.x * 8 + (threadIdx.x >> 5);
    int lane = threadIdx.x & 31;
    int s = g_slot[t];
    float gt = (s >= 0) ? g_gate[t] : 0.f;
    int ss = (s >= 0) ? s : 0;
    float a0 = 0, a1 = 0, a2 = 0, sv = 0;
    const float* zr = g_z + (size_t)t * 128;
#pragma unroll
    for (int i = 0; i < 4; i++) {
        int k = lane + i * 32;
        float zz = zr[k];
        a0 = fmaf(zz, wc[k * 3 + 0], a0);
        a1 = fmaf(zz, wc[k * 3 + 1], a1);
        a2 = fmaf(zz, wc[k * 3 + 2], a2);
    }
    const float* hr = g_buf2 + (size_t)ss * 256;   // relu(h7)
#pragma unroll
    for (int i = 0; i < 8; i++) {
        int k = lane + i * 32;
        sv = fmaf(fmaxf(hr[k], 0.f), ws[k], sv);
    }
#pragma unroll
    for (int o = 16; o; o >>= 1) {
        a0 += __shfl_xor_sync(0xffffffffu, a0, o);
        a1 += __shfl_xor_sync(0xffffffffu, a1, o);
        a2 += __shfl_xor_sync(0xffffffffu, a2, o);
        sv += __shfl_xor_sync(0xffffffffu, sv, o);
    }
    if (lane == 0) {
        float r0 = a0 + bc[0], r1 = a1 + bc[1], r2 = a2 + bc[2];
        out[t * 4 + 0] = 1.f / (1.f + expf(-r0));
        out[t * 4 + 1] = 1.f / (1.f + expf(-r1));
        out[t * 4 + 2] = 1.f / (1.f + expf(-r2));
        float sp = fmaf(gt, sv, bs[0]);
        out[t * 4 + 3] = fmaxf(sp, 0.f) + log1pf(expf(-fabsf(sp)));
    }
}

// ---------------- mma.sync bf16x3 GEMM, 2-stage cp.async pipeline ----------------
// dynamic smem: 2 stages x 4 buffers (Ah,Al,Bh,Bl) x 128x40 bf16 = 81920 B
#define TBUFB 10240          // bytes per buffer
template<int AMODE, int EXPERT, int SLOTM, int RELU, int WF32, int WSPLIT, int HASBIAS>
__global__ void __launch_bounds__(256, 2)
mma_gemm(const __nv_bfloat16* __restrict__ Ah, const __nv_bfloat16* __restrict__ Al,
         const __nv_bfloat16* __restrict__ A2h, const __nv_bfloat16* __restrict__ A2l,
         const __nv_bfloat16* __restrict__ Wh, const __nv_bfloat16* __restrict__ Wl,
         const float* __restrict__ bias,
         float* __restrict__ outf, __nv_bfloat16* __restrict__ oh, __nv_bfloat16* __restrict__ ol,
         int lda, int Kfull, int KCH, int ldc, long wstride, int bstride,
         const int* __restrict__ perm, const int* __restrict__ off) {
    extern __shared__ __align__(16) __nv_bfloat16 dsm[];
    __shared__ int sperm[128];

    const int m0 = blockIdx.x * 128, n0 = blockIdx.y * 128;
    int e = 0;
    if (SLOTM) {
        if (m0 >= off[8]) return;
        if (EXPERT) {
#pragma unroll
            for (int q = 0; q < 7; q++) if (m0 >= off[q + 1]) e = q + 1;
        }
    }
    const int tid = threadIdx.x, lane = tid & 31, wid = tid >> 5;
    const int wm = (wid & 3) * 32, wn = (wid >> 2) * 64;

    if (AMODE >= 1 && tid < 128) sperm[tid] = perm[m0 + tid];
    if (AMODE >= 1) __syncthreads();

    const __nv_bfloat16* wph = Wh + (EXPERT ? (long)e * wstride : 0);
    const __nv_bfloat16* wpl = Wl + (EXPERT ? (long)e * wstride : 0);

    const uint32_t sb = smem_u32(dsm);
    const int a_r = lane & 15, a_c = (lane & 16) >> 1;
    const int b_r = ((lane >> 4) << 3) + (lane & 7), b_c = lane & 8;

    auto issue = [&](int kc, int st) {
        uint32_t base = sb + st * (4 * TBUFB);
#pragma unroll
        for (int i = 0; i < 2; i++) {
            int u = tid + i * 256;
            int row = u >> 2, seg = u & 3;
            const __nv_bfloat16 *ph, *pl;
            if (AMODE == 2) {
                if (kc < 8) {
                    long r = sperm[row];
                    ph = Ah + r * 256 + kc * 32 + seg * 8;
                    pl = Al + r * 256 + kc * 32 + seg * 8;
                } else {
                    long r = m0 + row;
                    ph = A2h + r * 256 + (kc - 8) * 32 + seg * 8;
                    pl = A2l + r * 256 + (kc - 8) * 32 + seg * 8;
                }
            } else {
                long r = (AMODE == 1) ? sperm[row] : (m0 + row);
                ph = Ah + r * lda + kc * 32 + seg * 8;
                pl = Al + r * lda + kc * 32 + seg * 8;
            }
            uint32_t so = row * 80 + seg * 16;
            cpa16(base + 0 * TBUFB + so, ph);
            cpa16(base + 1 * TBUFB + so, pl);
            cpa16(base + 2 * TBUFB + so, wph + (long)(n0 + row) * Kfull + kc * 32 + seg * 8);
            cpa16(base + 3 * TBUFB + so, wpl + (long)(n0 + row) * Kfull + kc * 32 + seg * 8);
        }
    };

    float c[2][8][4];
#pragma unroll
    for (int i = 0; i < 2; i++)
#pragma unroll
        for (int j = 0; j < 8; j++)
#pragma unroll
            for (int q = 0; q < 4; q++) c[i][j][q] = 0.f;

    issue(0, 0);
    CP_COMMIT();

    for (int kc = 0; kc < KCH; kc++) {
        int cs = kc & 1;
        if (kc + 1 < KCH) { issue(kc + 1, cs ^ 1); CP_COMMIT(); CP_WAIT1(); }
        else CP_WAIT0();
        __syncthreads();

        uint32_t bA_h = sb + cs * (4 * TBUFB) + 0 * TBUFB;
        uint32_t bA_l = bA_h + TBUFB;
        uint32_t bB_h = bA_h + 2 * TBUFB;
        uint32_t bB_l = bA_h + 3 * TBUFB;
#pragma unroll
        for (int kt = 0; kt < 2; kt++) {
            uint32_t ahf[2][4], alf[2][4];
#pragma unroll
            for (int mt = 0; mt < 2; mt++) {
                uint32_t offa = ((wm + mt * 16 + a_r) * 40 + kt * 16 + a_c) * 2;
                ldsm4(ahf[mt], bA_h + offa);
                ldsm4(alf[mt], bA_l + offa);
            }
#pragma unroll
            for (int ng = 0; ng < 4; ng++) {
                uint32_t bh[4], bl[4];
                uint32_t offb = ((wn + ng * 16 + b_r) * 40 + kt * 16 + b_c) * 2;
                ldsm4(bh, bB_h + offb);
                ldsm4(bl, bB_l + offb);
#pragma unroll
                for (int mt = 0; mt < 2; mt++)
#pragma unroll
                    for (int ns = 0; ns < 2; ns++) {
                        float* cc = c[mt][ng * 2 + ns];
                        mma_bf16(cc, ahf[mt], bh + ns * 2);
                        mma_bf16(cc, ahf[mt], bl + ns * 2);
                        mma_bf16(cc, alf[mt], bh + ns * 2);
                    }
            }
        }
        __syncthreads();
    }

#pragma unroll
    for (int mt = 0; mt < 2; mt++)
#pragma unroll
        for (int nt = 0; nt < 8; nt++) {
            int col = n0 + wn + nt * 8 + (lane & 3) * 2;
            float bv0 = 0.f, bv1 = 0.f;
            if (HASBIAS) {
                const float* bp = bias + (EXPERT ? e * bstride : 0) + col;
                bv0 = bp[0]; bv1 = bp[1];
            }
#pragma unroll
            for (int half = 0; half < 2; half++) {
                long row = m0 + wm + mt * 16 + (lane >> 2) + half * 8;
                float v0 = c[mt][nt][half * 2 + 0] + bv0;
                float v1 = c[mt][nt][half * 2 + 1] + bv1;
                if (RELU) { v0 = fmaxf(v0, 0.f); v1 = fmaxf(v1, 0.f); }
                if (WF32) {
                    outf[row * ldc + col] = v0;
                    outf[row * ldc + col + 1] = v1;
                }
                if (WSPLIT) {
                    __nv_bfloat16 h0_, l0_, h1_, l1_;
                    split2(v0, h0_, l0_); split2(v1, h1_, l1_);
                    oh[row * 256 + col] = h0_;     ol[row * 256 + col] = l0_;
                    oh[row * 256 + col + 1] = h1_; ol[row * 256 + col + 1] = l1_;
                }
            }
        }
}

// ---------------- launch ----------------
extern "C" void kernel_launch(void* const* d_in, const int* in_sizes, int n_in,
                              void* d_out, int out_size) {
    (void)in_sizes; (void)n_in; (void)out_size;
    const float* x     = (const float*)d_in[0];
    const float* emb_a = (const float*)d_in[1];
    const float* w_xyz = (const float*)d_in[2];
    const float* b_xyz = (const float*)d_in[3];
    const float* wg1   = (const float*)d_in[4];
    const float* bg1   = (const float*)d_in[5];
    const float* wg2   = (const float*)d_in[6];
    const float* bg2   = (const float*)d_in[7];
    const float* ln_g  = (const float*)d_in[8];
    const float* ln_b  = (const float*)d_in[9];
    const float* wg    = (const float*)d_in[10];
    const float* eW_a  = (const float*)d_in[11];
    const float* eb_a  = (const float*)d_in[12];
    const float* eW3   = (const float*)d_in[13];
    const float* eb3   = (const float*)d_in[14];
    const float* eW_b  = (const float*)d_in[15];
    const float* eb_b  = (const float*)d_in[16];
    const float* w1    = (const float*)d_in[17];
    const float* b1    = (const float*)d_in[18];
    const float* w2    = (const float*)d_in[19];
    const float* b2    = (const float*)d_in[20];
    const float* ws    = (const float*)d_in[21];
    const float* bs    = (const float*)d_in[22];
    const float* wc    = (const float*)d_in[23];
    const float* bc    = (const float*)d_in[24];
    const int*   cap   = (const int*)d_in[25];
    float* out = (float*)d_out;

    float *b1f, *b2f, *z;
    __nv_bfloat16 *peh, *pel, *h0h, *h0l, *p1h, *p1l, *p2h, *p2l, *cath, *catl;
    __nv_bfloat16 *wxh, *wxl, *wg1h, *wg1l, *wg2h, *wg2l;
    __nv_bfloat16 *wah, *wal, *w3h, *w3l, *wbh, *wbl, *w1h, *w1l, *w2h, *w2l;
    int *perm, *off;
    cudaGetSymbolAddress((void**)&b1f, g_buf1);  cudaGetSymbolAddress((void**)&b2f, g_buf2);
    cudaGetSymbolAddress((void**)&z, g_z);
    cudaGetSymbolAddress((void**)&peh, g_peh);   cudaGetSymbolAddress((void**)&pel, g_pel);
    cudaGetSymbolAddress((void**)&h0h, g_h0h);   cudaGetSymbolAddress((void**)&h0l, g_h0l);
    cudaGetSymbolAddress((void**)&p1h, g_p1h);   cudaGetSymbolAddress((void**)&p1l, g_p1l);
    cudaGetSymbolAddress((void**)&p2h, g_p2h);   cudaGetSymbolAddress((void**)&p2l, g_p2l);
    cudaGetSymbolAddress((void**)&cath, g_cath); cudaGetSymbolAddress((void**)&catl, g_catl);
    cudaGetSymbolAddress((void**)&wxh, g_wxh);   cudaGetSymbolAddress((void**)&wxl, g_wxl);
    cudaGetSymbolAddress((void**)&wg1h, g_wg1h); cudaGetSymbolAddress((void**)&wg1l, g_wg1l);
    cudaGetSymbolAddress((void**)&wg2h, g_wg2h); cudaGetSymbolAddress((void**)&wg2l, g_wg2l);
    cudaGetSymbolAddress((void**)&wah, g_wah);   cudaGetSymbolAddress((void**)&wal, g_wal);
    cudaGetSymbolAddress((void**)&w3h, g_w3h);   cudaGetSymbolAddress((void**)&w3l, g_w3l);
    cudaGetSymbolAddress((void**)&wbh, g_wbh);   cudaGetSymbolAddress((void**)&wbl, g_wbl);
    cudaGetSymbolAddress((void**)&w1h, g_w1h);   cudaGetSymbolAddress((void**)&w1l, g_w1l);
    cudaGetSymbolAddress((void**)&w2h, g_w2h);   cudaGetSymbolAddress((void**)&w2l, g_w2l);
    cudaGetSymbolAddress((void**)&perm, g_perm); cudaGetSymbolAddress((void**)&off, g_off);

    const int SMEMP = 81920;
    cudaFuncSetAttribute((const void*)mma_gemm<0,0,0,0,0,1,1>, cudaFuncAttributeMaxDynamicSharedMemorySize, SMEMP);
    cudaFuncSetAttribute((const void*)mma_gemm<0,0,0,1,0,1,1>, cudaFuncAttributeMaxDynamicSharedMemorySize, SMEMP);
    cudaFuncSetAttribute((const void*)mma_gemm<0,0,0,0,1,0,1>, cudaFuncAttributeMaxDynamicSharedMemorySize, SMEMP);
    cudaFuncSetAttribute((const void*)mma_gemm<1,1,1,1,0,1,1>, cudaFuncAttributeMaxDynamicSharedMemorySize, SMEMP);
    cudaFuncSetAttribute((const void*)mma_gemm<0,1,1,1,0,1,1>, cudaFuncAttributeMaxDynamicSharedMemorySize, SMEMP);
    cudaFuncSetAttribute((const void*)mma_gemm<2,1,1,1,0,1,1>, cudaFuncAttributeMaxDynamicSharedMemorySize, SMEMP);
    cudaFuncSetAttribute((const void*)mma_gemm<0,1,1,1,1,1,1>, cudaFuncAttributeMaxDynamicSharedMemorySize, SMEMP);
    cudaFuncSetAttribute((const void*)mma_gemm<0,0,1,0,1,0,0>, cudaFuncAttributeMaxDynamicSharedMemorySize, SMEMP);
    cudaFuncSetAttribute((const void*)mma_gemm<0,0,0,1,1,0,1>, cudaFuncAttributeMaxDynamicSharedMemorySize, SMEMP);

    k_reset<<<MMAX / 256, 256>>>();
    k_pe<<<(NTOK * 40 + 255) / 256, 256>>>(x);

    // weight transposes + bf16 splits
    k_wt<<<dim3(3, 8, 1),  dim3(32, 8)>>>(w_xyz, wxh, wxl, 75, 256, 96, 19200, 24576);
    k_wt<<<dim3(8, 8, 1),  dim3(32, 8)>>>(wg1, wg1h, wg1l, 256, 256, 256, 65536, 65536);
    k_wt<<<dim3(8, 8, 1),  dim3(32, 8)>>>(wg2, wg2h, wg2l, 256, 256, 256, 65536, 65536);
    k_wt<<<dim3(8, 8, 24), dim3(32, 8)>>>(eW_a, wah, wal, 256, 256, 256, 65536, 65536);
    k_wt<<<dim3(16, 8, 8), dim3(32, 8)>>>(eW3, w3h, w3l, 512, 256, 512, 131072, 131072);
    k_wt<<<dim3(8, 8, 24), dim3(32, 8)>>>(eW_b, wbh, wbl, 256, 256, 256, 65536, 65536);
    k_wt<<<dim3(8, 8, 1),  dim3(32, 8)>>>(w1, w1h, w1l, 256, 256, 256, 65536, 65536);
    k_wt<<<dim3(12, 4, 1), dim3(32, 8)>>>(w2, w2h, w2l, 331, 128, 384, 42368, 49152);

    // backbone (bf16x3; argmax protected by margin-gated exact recompute)
    dim3 gT(NTOK / 128, 2);
    mma_gemm<0,0,0,0,0,1,1><<<gT, 256, SMEMP>>>(peh, pel, nullptr, nullptr, wxh, wxl, b_xyz,
        nullptr, h0h, h0l, 96, 96, 3, 256, 0, 0, nullptr, nullptr);
    mma_gemm<0,0,0,1,0,1,1><<<gT, 256, SMEMP>>>(h0h, h0l, nullptr, nullptr, wg1h, wg1l, bg1,
        nullptr, p1h, p1l, 256, 256, 8, 256, 0, 0, nullptr, nullptr);
    mma_gemm<0,0,0,0,1,0,1><<<gT, 256, SMEMP>>>(p1h, p1l, nullptr, nullptr, wg2h, wg2l, bg2,
        b2f, nullptr, nullptr, 256, 256, 8, 256, 0, 0, nullptr, nullptr);

    // routing
    k_gate<<<NTOK / 8, 256>>>(ln_g, ln_b, wg);
    k_exact<<<256, 256>>>(x, w_xyz, b_xyz, wg1, bg1, wg2, bg2, ln_g, ln_b, wg);
    k_hist<<<512, 256>>>();
    k_scan<<<1, 32>>>(cap);
    k_loc<<<512, 32>>>(cap);

    // expert chain
    dim3 gS(MMAX / 128, 2);
    mma_gemm<1,1,1,1,0,1,1><<<gS, 256, SMEMP>>>(h0h, h0l, nullptr, nullptr, wah, wal, eb_a,
        nullptr, p1h, p1l, 256, 256, 8, 256, 196608, 768, perm, off);
    mma_gemm<0,1,1,1,0,1,1><<<gS, 256, SMEMP>>>(p1h, p1l, nullptr, nullptr, wah + 65536, wal + 65536, eb_a + 256,
        nullptr, p2h, p2l, 256, 256, 8, 256, 196608, 768, perm, off);
    mma_gemm<0,1,1,1,0,1,1><<<gS, 256, SMEMP>>>(p2h, p2l, nullptr, nullptr, wah + 131072, wal + 131072, eb_a + 512,
        nullptr, p1h, p1l, 256, 256, 8, 256, 196608, 768, perm, off);
    mma_gemm<2,1,1,1,0,1,1><<<gS, 256, SMEMP>>>(h0h, h0l, p1h, p1l, w3h, w3l, eb3,
        nullptr, p2h, p2l, 256, 512, 16, 256, 131072, 256, perm, off);
    mma_gemm<0,1,1,1,0,1,1><<<gS, 256, SMEMP>>>(p2h, p2l, nullptr, nullptr, wbh, wbl, eb_b,
        nullptr, p1h, p1l, 256, 256, 8, 256, 196608, 768, perm, off);
    mma_gemm<0,1,1,1,0,1,1><<<gS, 256, SMEMP>>>(p1h, p1l, nullptr, nullptr, wbh + 65536, wbl + 65536, eb_b + 256,
        nullptr, p2h, p2l, 256, 256, 8, 256, 196608, 768, perm, off);
    mma_gemm<0,1,1,1,1,1,1><<<gS, 256, SMEMP>>>(p2h, p2l, nullptr, nullptr, wbh + 131072, wbl + 131072, eb_b + 512,
        b2f, p1h, p1l, 256, 256, 8, 256, 196608, 768, perm, off);
    mma_gemm<0,0,1,0,1,0,0><<<gS, 256, SMEMP>>>(p1h, p1l, nullptr, nullptr, w1h, w1l, nullptr,
        b1f, nullptr, nullptr, 256, 256, 8, 256, 0, 0, perm, off);

    // heads
    k_cat<<<NTOK, 128>>>(x, emb_a, b1);
    mma_gemm<0,0,0,1,1,0,1><<<dim3(NTOK / 128, 1), 256, SMEMP>>>(cath, catl, nullptr, nullptr, w2h, w2l, b2,
        z, nullptr, nullptr, 384, 384, 12, 128, 0, 0, perm, off);
    k_final<<<NTOK / 8, 256>>>(wc, bc, ws, bs, out);
}

// round 15
// speedup vs baseline: 1.0178x; 1.0117x over previous
#include <cuda_runtime.h>
#include <cuda_bf16.h>
#include <math.h>
#include <stdint.h>

#define NTOK 131072
#define MMAX 132096   // NTOK + 8*128 padding

// ---------------- device scratch (static; no allocation) ----------------
__device__ float g_buf1[33816576];   // u (w1 out)
__device__ float g_buf2[33816576];   // ext (gate in) then relu(h7)
__device__ float g_z[16777216];      // NTOK x 128
__device__ __nv_bfloat16 g_peh[12582912], g_pel[12582912];   // NTOK x 96 posenc split
__device__ __nv_bfloat16 g_h0h[33554432], g_h0l[33554432];   // split h0
__device__ __nv_bfloat16 g_p1h[33816576], g_p1l[33816576];   // act ping
__device__ __nv_bfloat16 g_p2h[33816576], g_p2l[33816576];   // act pong
__device__ __nv_bfloat16 g_cath[50331648], g_catl[50331648]; // NTOK x 384
__device__ __nv_bfloat16 g_wxh[24576],  g_wxl[24576];        // w_xyz^T [256,96]
__device__ __nv_bfloat16 g_wg1h[65536], g_wg1l[65536];       // wg1^T
__device__ __nv_bfloat16 g_wg2h[65536], g_wg2l[65536];       // wg2^T
__device__ __nv_bfloat16 g_wah[1572864], g_wal[1572864];     // eW_a^T  24 x [256,256]
__device__ __nv_bfloat16 g_w3h[1048576], g_w3l[1048576];     // eW3^T    8 x [256,512]
__device__ __nv_bfloat16 g_wbh[1572864], g_wbl[1572864];     // eW_b^T
__device__ __nv_bfloat16 g_w1h[65536],  g_w1l[65536];        // w1^T
__device__ __nv_bfloat16 g_w2h[49152],  g_w2l[49152];        // w2^T [128,384]
__device__ float g_gate[NTOK];
__device__ int   g_eidx[NTOK], g_slot[NTOK], g_perm[MMAX];
__device__ int   g_hist[4096], g_base[4096], g_counts[8], g_off[9];
__device__ int   g_fcnt;
__device__ int   g_flist[NTOK];

// ---------------- helpers ----------------
__device__ __forceinline__ uint32_t smem_u32(const void* p) {
    uint32_t a;
    asm("{ .reg .u64 t; cvta.to.shared.u64 t, %1; cvt.u32.u64 %0, t; }" : "=r"(a) : "l"(p));
    return a;
}
__device__ __forceinline__ void ldsm4(uint32_t* r, uint32_t addr) {
    asm volatile("ldmatrix.sync.aligned.m8n8.x4.shared.b16 {%0,%1,%2,%3}, [%4];"
                 : "=r"(r[0]), "=r"(r[1]), "=r"(r[2]), "=r"(r[3]) : "r"(addr));
}
__device__ __forceinline__ void mma_bf16(float* c, const uint32_t* a, const uint32_t* b) {
    asm volatile("mma.sync.aligned.m16n8k16.row.col.f32.bf16.bf16.f32 "
                 "{%0,%1,%2,%3}, {%4,%5,%6,%7}, {%8,%9}, {%0,%1,%2,%3};"
                 : "+f"(c[0]), "+f"(c[1]), "+f"(c[2]), "+f"(c[3])
                 : "r"(a[0]), "r"(a[1]), "r"(a[2]), "r"(a[3]), "r"(b[0]), "r"(b[1]));
}
__device__ __forceinline__ void cpa16(uint32_t dst, const void* src) {
    asm volatile("cp.async.cg.shared.global [%0], [%1], 16;" :: "r"(dst), "l"(src));
}
#define CP_COMMIT() asm volatile("cp.async.commit_group;" ::: "memory")
#define CP_WAIT1()  asm volatile("cp.async.wait_group 1;" ::: "memory")
#define CP_WAIT0()  asm volatile("cp.async.wait_group 0;" ::: "memory")
__device__ __forceinline__ void split2(float v, __nv_bfloat16& h, __nv_bfloat16& l) {
    h = __float2bfloat16_rn(v);
    l = __float2bfloat16_rn(v - __bfloat162float(h));
}
__device__ __forceinline__ float pe_val(const float* xr, int k) {
    if (k < 3) return xr[k];
    int r = k - 3, f = r / 6, q = r % 6, d = q % 3, s = q / 3;
    float arg = xr[d] * (float)(1 << f);
    return s ? cosf(arg) : sinf(arg);
}

// ---------------- small kernels ----------------
__global__ void k_reset() {
    int i = blockIdx.x * 256 + threadIdx.x;
    if (i < MMAX) g_perm[i] = 0;
    if (i == 0) g_fcnt = 0;
}

__global__ void k_pe(const float* __restrict__ x) {
    int idx = blockIdx.x * 256 + threadIdx.x;
    if (idx >= NTOK * 40) return;
    int t = idx / 40, r = idx - t * 40;
    size_t base = (size_t)t * 96;
    __nv_bfloat16 h, l;
    if (r < 3) {
        split2(x[t * 7 + r], h, l);
        g_peh[base + r] = h; g_pel[base + r] = l;
    } else if (r < 39) {
        int p = r - 3, f = p / 3, d = p % 3;
        float s, c;
        sincosf(x[t * 7 + d] * (float)(1 << f), &s, &c);
        int ks = 3 + f * 6 + d, kc = ks + 3;
        split2(s, h, l); g_peh[base + ks] = h; g_pel[base + ks] = l;
        split2(c, h, l); g_peh[base + kc] = h; g_pel[base + kc] = l;
    } else {
        __nv_bfloat16 z = __float2bfloat16(0.f);
        for (int c = 75; c < 96; c++) { g_peh[base + c] = z; g_pel[base + c] = z; }
    }
}

__global__ void k_wt(const float* __restrict__ src, __nv_bfloat16* __restrict__ dh,
                     __nv_bfloat16* __restrict__ dl, int K, int N, int Kpad,
                     long sstride, long dstride) {
    __shared__ float t[32][33];
    int b = blockIdx.z, k0 = blockIdx.x * 32, n0 = blockIdx.y * 32;
#pragma unroll
    for (int i = 0; i < 32; i += 8) {
        int k = k0 + threadIdx.y + i, n = n0 + threadIdx.x;
        t[threadIdx.y + i][threadIdx.x] = (k < K) ? src[b * sstride + (long)k * N + n] : 0.f;
    }
    __syncthreads();
#pragma unroll
    for (int i = 0; i < 32; i += 8) {
        int n = n0 + threadIdx.y + i, k = k0 + threadIdx.x;
        float v = t[threadIdx.x][threadIdx.y + i];
        __nv_bfloat16 h, l; split2(v, h, l);
        long o = b * dstride + (long)n * Kpad + k;
        dh[o] = h; dl[o] = l;
    }
}

__global__ void k_gate(const float* __restrict__ lng, const float* __restrict__ lnb,
                       const float* __restrict__ wg) {
    int t = blockIdx.x * 8 + (threadIdx.x >> 5);
    int lane = threadIdx.x & 31;
    const float* row = g_buf2 + (size_t)t * 256;
    float xv[8], s = 0.f;
#pragma unroll
    for (int i = 0; i < 8; i++) { xv[i] = row[lane + i * 32]; s += xv[i]; }
#pragma unroll
    for (int o = 16; o; o >>= 1) s += __shfl_xor_sync(0xffffffffu, s, o);
    float mean = s * (1.f / 256.f), vv = 0.f;
#pragma unroll
    for (int i = 0; i < 8; i++) { float d = xv[i] - mean; vv += d * d; }
#pragma unroll
    for (int o = 16; o; o >>= 1) vv += __shfl_xor_sync(0xffffffffu, vv, o);
    float rstd = rsqrtf(vv * (1.f / 256.f) + 1e-5f);
    float l[8] = {0,0,0,0,0,0,0,0};
#pragma unroll
    for (int i = 0; i < 8; i++) {
        int k = lane + i * 32;
        float ln = (xv[i] - mean) * rstd * lng[k] + lnb[k];
#pragma unroll
        for (int e = 0; e < 8; e++) l[e] = fmaf(ln, wg[k * 8 + e], l[e]);
    }
#pragma unroll
    for (int o = 16; o; o >>= 1)
#pragma unroll
        for (int e = 0; e < 8; e++) l[e] += __shfl_xor_sync(0xffffffffu, l[e], o);
    if (lane == 0) {
        float best = -1e30f, second = -1e30f; int bi = 0;
#pragma unroll
        for (int e = 0; e < 8; e++) {
            float v = l[e];
            if (v > best) { second = best; best = v; bi = e; }
            else if (v > second) second = v;
        }
        float se = 0.f;
#pragma unroll
        for (int e = 0; e < 8; e++) se += expf(l[e] - best);
        g_eidx[t] = bi; g_gate[t] = 1.f / se;
        if (best - second < 2e-3f) {
            int i = atomicAdd(&g_fcnt, 1);
            g_flist[i] = t;
        }
    }
}

__global__ void k_exact(const float* __restrict__ x,
                        const float* __restrict__ w_xyz, const float* __restrict__ b_xyz,
                        const float* __restrict__ wg1, const float* __restrict__ bg1,
                        const float* __restrict__ wg2, const float* __restrict__ bg2,
                        const float* __restrict__ lng, const float* __restrict__ lnb,
                        const float* __restrict__ wg) {
    __shared__ float pe[80], h0[256], f1[256], f2[256], ln[256], sred[256];
    int tid = threadIdx.x;
    for (int fi = blockIdx.x; fi < g_fcnt; fi += gridDim.x) {
        int t = g_flist[fi];
        if (tid < 75) pe[tid] = pe_val(x + t * 7, tid);
        __syncthreads();
        float a = b_xyz[tid];
        for (int k = 0; k < 75; k++) a = fmaf(pe[k], w_xyz[k * 256 + tid], a);
        h0[tid] = a;
        __syncthreads();
        a = bg1[tid];
        for (int k = 0; k < 256; k++) a = fmaf(h0[k], wg1[k * 256 + tid], a);
        f1[tid] = fmaxf(a, 0.f);
        __syncthreads();
        a = bg2[tid];
        for (int k = 0; k < 256; k++) a = fmaf(f1[k], wg2[k * 256 + tid], a);
        f2[tid] = a;
        sred[tid] = a;
        __syncthreads();
        for (int s = 128; s; s >>= 1) { if (tid < s) sred[tid] += sred[tid + s]; __syncthreads(); }
        float mean = sred[0] * (1.f / 256.f);
        __syncthreads();
        float d = f2[tid] - mean;
        sred[tid] = d * d;
        __syncthreads();
        for (int s = 128; s; s >>= 1) { if (tid < s) sred[tid] += sred[tid + s]; __syncthreads(); }
        float rstd = rsqrtf(sred[0] * (1.f / 256.f) + 1e-5f);
        __syncthreads();
        ln[tid] = (f2[tid] - mean) * rstd * lng[tid] + lnb[tid];
        __syncthreads();
        if (tid < 32) {
            int lane = tid;
            float l[8] = {0,0,0,0,0,0,0,0};
#pragma unroll
            for (int i = 0; i < 8; i++) {
                int k = lane + i * 32;
                float lv = ln[k];
#pragma unroll
                for (int e = 0; e < 8; e++) l[e] = fmaf(lv, wg[k * 8 + e], l[e]);
            }
#pragma unroll
            for (int o = 16; o; o >>= 1)
#pragma unroll
                for (int e = 0; e < 8; e++) l[e] += __shfl_xor_sync(0xffffffffu, l[e], o);
            if (lane == 0) {
                float best = l[0]; int bi = 0;
#pragma unroll
                for (int e = 1; e < 8; e++) if (l[e] > best) { best = l[e]; bi = e; }
                float se = 0.f;
#pragma unroll
                for (int e = 0; e < 8; e++) se += expf(l[e] - best);
                g_eidx[t] = bi; g_gate[t] = 1.f / se;
            }
        }
        __syncthreads();
    }
}

__global__ void k_hist() {
    __shared__ int h[8];
    if (threadIdx.x < 8) h[threadIdx.x] = 0;
    __syncthreads();
    atomicAdd(&h[g_eidx[blockIdx.x * 256 + threadIdx.x]], 1);
    __syncthreads();
    if (threadIdx.x < 8) g_hist[blockIdx.x * 8 + threadIdx.x] = h[threadIdx.x];
}

__global__ void k_scan(const int* __restrict__ cap) {
    int e = threadIdx.x;
    if (e < 8) {
        int run = 0;
        for (int b = 0; b < 512; b++) { g_base[b * 8 + e] = run; run += g_hist[b * 8 + e]; }
        g_counts[e] = run;
    }
    __syncthreads();
    if (threadIdx.x == 0) {
        int c = cap[0], o = 0;
        g_off[0] = 0;
        for (int q = 0; q < 8; q++) {
            int kc = g_counts[q]; if (kc > c) kc = c;
            o += ((kc + 127) >> 7) << 7;
            g_off[q + 1] = o;
        }
    }
}

__global__ void k_loc(const int* __restrict__ cap) {
    int b = blockIdx.x, e = threadIdx.x;
    if (e >= 8) return;
    int run = g_base[b * 8 + e], o = g_off[e], c = cap[0];
    for (int i = 0; i < 256; i++) {
        int t = b * 256 + i;
        if (g_eidx[t] == e) {
            if (run < c) { int s = o + run; g_perm[s] = t; g_slot[t] = s; }
            else g_slot[t] = -1;
            run++;
        }
    }
}

__global__ void k_cat(const float* __restrict__ x, const float* __restrict__ emb,
                      const float* __restrict__ b1) {
    int t = blockIdx.x, j = threadIdx.x;
    int s = g_slot[t];
    float gt = (s >= 0) ? g_gate[t] : 0.f;
    int ss = (s >= 0) ? s : 0;
    size_t base = (size_t)t * 384;
    const float* ub = g_buf1 + (size_t)ss * 256;
    __nv_bfloat16 h, l;
    float v0 = fmaf(gt, ub[j], b1[j]);
    split2(v0, h, l); g_cath[base + j] = h; g_catl[base + j] = l;
    float v1 = fmaf(gt, ub[128 + j], b1[128 + j]);
    split2(v1, h, l); g_cath[base + 128 + j] = h; g_catl[base + 128 + j] = l;
    if (j < 3) {
        split2(x[t * 7 + 3 + j], h, l);
        g_cath[base + 256 + j] = h; g_catl[base + 256 + j] = l;
    } else if (j < 15) {
        int p = j - 3, f = p / 3, d = p % 3;
        float sv, cv;
        sincosf(x[t * 7 + 3 + d] * (float)(1 << f), &sv, &cv);
        int ks = 256 + 3 + f * 6 + d, kc = ks + 3;
        split2(sv, h, l); g_cath[base + ks] = h; g_catl[base + ks] = l;
        split2(cv, h, l); g_cath[base + kc] = h; g_catl[base + kc] = l;
    }
    if (j < 48) {
        int a = (int)x[t * 7 + 6];
        split2(emb[a * 48 + j], h, l);
        g_cath[base + 283 + j] = h; g_catl[base + 283 + j] = l;
    }
    if (j < 53) { g_cath[base + 331 + j] = __float2bfloat16(0.f); g_catl[base + 331 + j] = __float2bfloat16(0.f); }
}

__global__ void k_final(const float* __restrict__ wc, const float* __restrict__ bc,
                        const float* __restrict__ ws, const float* __restrict__ bs,
                        float* __restrict__ out) {
    int t = blockIdx.x * 8 + (threadIdx.x >> 5);
    int lane = threadIdx.x & 31;
    int s = g_slot[t];
    float gt = (s >= 0) ? g_gate[t] : 0.f;
    int ss = (s >= 0) ? s : 0;
    float a0 = 0, a1 = 0, a2 = 0, sv = 0;
    const float* zr = g_z + (size_t)t * 128;
#pragma unroll
    for (int i = 0; i < 4; i++) {
        int k = lane + i * 32;
        float zz = zr[k];
        a0 = fmaf(zz, wc[k * 3 + 0], a0);
        a1 = fmaf(zz, wc[k * 3 + 1], a1);
        a2 = fmaf(zz, wc[k * 3 + 2], a2);
    }
    const float* hr = g_buf2 + (size_t)ss * 256;   // relu(h7)
#pragma unroll
    for (int i = 0; i < 8; i++) {
        int k = lane + i * 32;
        sv = fmaf(fmaxf(hr[k], 0.f), ws[k], sv);
    }
#pragma unroll
    for (int o = 16; o; o >>= 1) {
        a0 += __shfl_xor_sync(0xffffffffu, a0, o);
        a1 += __shfl_xor_sync(0xffffffffu, a1, o);
        a2 += __shfl_xor_sync(0xffffffffu, a2, o);
        sv += __shfl_xor_sync(0xffffffffu, sv, o);
    }
    if (lane == 0) {
        float r0 = a0 + bc[0], r1 = a1 + bc[1], r2 = a2 + bc[2];
        out[t * 4 + 0] = 1.f / (1.f + expf(-r0));
        out[t * 4 + 1] = 1.f / (1.f + expf(-r1));
        out[t * 4 + 2] = 1.f / (1.f + expf(-r2));
        float sp = fmaf(gt, sv, bs[0]);
        out[t * 4 + 3] = fmaxf(sp, 0.f) + log1pf(expf(-fabsf(sp)));
    }
}

// ---------------- mma.sync bf16x3 GEMM, 2-stage cp.async pipeline ----------------
// MMA3=1: full hi/lo x3. MMA3=0: drop A-hi x B-lo term (B effectively bf16; w2 only).
#define TBUFB 10240
template<int AMODE, int EXPERT, int SLOTM, int RELU, int WF32, int WSPLIT, int HASBIAS, int MMA3>
__global__ void __launch_bounds__(256, 2)
mma_gemm(const __nv_bfloat16* __restrict__ Ah, const __nv_bfloat16* __restrict__ Al,
         const __nv_bfloat16* __restrict__ A2h, const __nv_bfloat16* __restrict__ A2l,
         const __nv_bfloat16* __restrict__ Wh, const __nv_bfloat16* __restrict__ Wl,
         const float* __restrict__ bias,
         float* __restrict__ outf, __nv_bfloat16* __restrict__ oh, __nv_bfloat16* __restrict__ ol,
         int lda, int Kfull, int KCH, int ldc, long wstride, int bstride,
         const int* __restrict__ perm, const int* __restrict__ off) {
    extern __shared__ __align__(16) __nv_bfloat16 dsm[];
    __shared__ int sperm[128];

    const int m0 = blockIdx.x * 128, n0 = blockIdx.y * 128;
    int e = 0;
    if (SLOTM) {
        if (m0 >= off[8]) return;
        if (EXPERT) {
#pragma unroll
            for (int q = 0; q < 7; q++) if (m0 >= off[q + 1]) e = q + 1;
        }
    }
    const int tid = threadIdx.x, lane = tid & 31, wid = tid >> 5;
    const int wm = (wid & 3) * 32, wn = (wid >> 2) * 64;

    if (AMODE >= 1 && tid < 128) sperm[tid] = perm[m0 + tid];
    if (AMODE >= 1) __syncthreads();

    const __nv_bfloat16* wph = Wh + (EXPERT ? (long)e * wstride : 0);
    const __nv_bfloat16* wpl = Wl + (EXPERT ? (long)e * wstride : 0);

    const uint32_t sb = smem_u32(dsm);
    const int a_r = lane & 15, a_c = (lane & 16) >> 1;
    const int b_r = ((lane >> 4) << 3) + (lane & 7), b_c = lane & 8;

    auto issue = [&](int kc, int st) {
        uint32_t base = sb + st * (4 * TBUFB);
#pragma unroll
        for (int i = 0; i < 2; i++) {
            int u = tid + i * 256;
            int row = u >> 2, seg = u & 3;
            const __nv_bfloat16 *ph, *pl;
            if (AMODE == 2) {
                if (kc < 8) {
                    long r = sperm[row];
                    ph = Ah + r * 256 + kc * 32 + seg * 8;
                    pl = Al + r * 256 + kc * 32 + seg * 8;
                } else {
                    long r = m0 + row;
                    ph = A2h + r * 256 + (kc - 8) * 32 + seg * 8;
                    pl = A2l + r * 256 + (kc - 8) * 32 + seg * 8;
                }
            } else {
                long r = (AMODE == 1) ? sperm[row] : (m0 + row);
                ph = Ah + r * lda + kc * 32 + seg * 8;
                pl = Al + r * lda + kc * 32 + seg * 8;
            }
            uint32_t so = row * 80 + seg * 16;
            cpa16(base + 0 * TBUFB + so, ph);
            cpa16(base + 1 * TBUFB + so, pl);
            cpa16(base + 2 * TBUFB + so, wph + (long)(n0 + row) * Kfull + kc * 32 + seg * 8);
            if (MMA3)
                cpa16(base + 3 * TBUFB + so, wpl + (long)(n0 + row) * Kfull + kc * 32 + seg * 8);
        }
    };

    float c[2][8][4];
#pragma unroll
    for (int i = 0; i < 2; i++)
#pragma unroll
        for (int j = 0; j < 8; j++)
#pragma unroll
            for (int q = 0; q < 4; q++) c[i][j][q] = 0.f;

    issue(0, 0);
    CP_COMMIT();

    for (int kc = 0; kc < KCH; kc++) {
        int cs = kc & 1;
        if (kc + 1 < KCH) { issue(kc + 1, cs ^ 1); CP_COMMIT(); CP_WAIT1(); }
        else CP_WAIT0();
        __syncthreads();

        uint32_t bA_h = sb + cs * (4 * TBUFB) + 0 * TBUFB;
        uint32_t bA_l = bA_h + TBUFB;
        uint32_t bB_h = bA_h + 2 * TBUFB;
        uint32_t bB_l = bA_h + 3 * TBUFB;
#pragma unroll
        for (int kt = 0; kt < 2; kt++) {
            uint32_t ahf[2][4], alf[2][4];
#pragma unroll
            for (int mt = 0; mt < 2; mt++) {
                uint32_t offa = ((wm + mt * 16 + a_r) * 40 + kt * 16 + a_c) * 2;
                ldsm4(ahf[mt], bA_h + offa);
                ldsm4(alf[mt], bA_l + offa);
            }
#pragma unroll
            for (int ng = 0; ng < 4; ng++) {
                uint32_t bh[4], bl[4];
                uint32_t offb = ((wn + ng * 16 + b_r) * 40 + kt * 16 + b_c) * 2;
                ldsm4(bh, bB_h + offb);
                if (MMA3) ldsm4(bl, bB_l + offb);
#pragma unroll
                for (int mt = 0; mt < 2; mt++)
#pragma unroll
                    for (int ns = 0; ns < 2; ns++) {
                        float* cc = c[mt][ng * 2 + ns];
                        mma_bf16(cc, ahf[mt], bh + ns * 2);
                        if (MMA3) mma_bf16(cc, ahf[mt], bl + ns * 2);
                        mma_bf16(cc, alf[mt], bh + ns * 2);
                    }
            }
        }
        __syncthreads();
    }

#pragma unroll
    for (int mt = 0; mt < 2; mt++)
#pragma unroll
        for (int nt = 0; nt < 8; nt++) {
            int col = n0 + wn + nt * 8 + (lane & 3) * 2;
            float bv0 = 0.f, bv1 = 0.f;
            if (HASBIAS) {
                const float* bp = bias + (EXPERT ? e * bstride : 0) + col;
                bv0 = bp[0]; bv1 = bp[1];
            }
#pragma unroll
            for (int half = 0; half < 2; half++) {
                long row = m0 + wm + mt * 16 + (lane >> 2) + half * 8;
                float v0 = c[mt][nt][half * 2 + 0] + bv0;
                float v1 = c[mt][nt][half * 2 + 1] + bv1;
                if (RELU) { v0 = fmaxf(v0, 0.f); v1 = fmaxf(v1, 0.f); }
                if (WF32) {
                    outf[row * ldc + col] = v0;
                    outf[row * ldc + col + 1] = v1;
                }
                if (WSPLIT) {
                    __nv_bfloat16 h0_, l0_, h1_, l1_;
                    split2(v0, h0_, l0_); split2(v1, h1_, l1_);
                    oh[row * 256 + col] = h0_;     ol[row * 256 + col] = l0_;
                    oh[row * 256 + col + 1] = h1_; ol[row * 256 + col + 1] = l1_;
                }
            }
        }
}

// ---------------- launch ----------------
extern "C" void kernel_launch(void* const* d_in, const int* in_sizes, int n_in,
                              void* d_out, int out_size) {
    (void)in_sizes; (void)n_in; (void)out_size;
    const float* x     = (const float*)d_in[0];
    const float* emb_a = (const float*)d_in[1];
    const float* w_xyz = (const float*)d_in[2];
    const float* b_xyz = (const float*)d_in[3];
    const float* wg1   = (const float*)d_in[4];
    const float* bg1   = (const float*)d_in[5];
    const float* wg2   = (const float*)d_in[6];
    const float* bg2   = (const float*)d_in[7];
    const float* ln_g  = (const float*)d_in[8];
    const float* ln_b  = (const float*)d_in[9];
    const float* wg    = (const float*)d_in[10];
    const float* eW_a  = (const float*)d_in[11];
    const float* eb_a  = (const float*)d_in[12];
    const float* eW3   = (const float*)d_in[13];
    const float* eb3   = (const float*)d_in[14];
    const float* eW_b  = (const float*)d_in[15];
    const float* eb_b  = (const float*)d_in[16];
    const float* w1    = (const float*)d_in[17];
    const float* b1    = (const float*)d_in[18];
    const float* w2    = (const float*)d_in[19];
    const float* b2    = (const float*)d_in[20];
    const float* ws    = (const float*)d_in[21];
    const float* bs    = (const float*)d_in[22];
    const float* wc    = (const float*)d_in[23];
    const float* bc    = (const float*)d_in[24];
    const int*   cap   = (const int*)d_in[25];
    float* out = (float*)d_out;

    float *b1f, *b2f, *z;
    __nv_bfloat16 *peh, *pel, *h0h, *h0l, *p1h, *p1l, *p2h, *p2l, *cath, *catl;
    __nv_bfloat16 *wxh, *wxl, *wg1h, *wg1l, *wg2h, *wg2l;
    __nv_bfloat16 *wah, *wal, *w3h, *w3l, *wbh, *wbl, *w1h, *w1l, *w2h, *w2l;
    int *perm, *off;
    cudaGetSymbolAddress((void**)&b1f, g_buf1);  cudaGetSymbolAddress((void**)&b2f, g_buf2);
    cudaGetSymbolAddress((void**)&z, g_z);
    cudaGetSymbolAddress((void**)&peh, g_peh);   cudaGetSymbolAddress((void**)&pel, g_pel);
    cudaGetSymbolAddress((void**)&h0h, g_h0h);   cudaGetSymbolAddress((void**)&h0l, g_h0l);
    cudaGetSymbolAddress((void**)&p1h, g_p1h);   cudaGetSymbolAddress((void**)&p1l, g_p1l);
    cudaGetSymbolAddress((void**)&p2h, g_p2h);   cudaGetSymbolAddress((void**)&p2l, g_p2l);
    cudaGetSymbolAddress((void**)&cath, g_cath); cudaGetSymbolAddress((void**)&catl, g_catl);
    cudaGetSymbolAddress((void**)&wxh, g_wxh);   cudaGetSymbolAddress((void**)&wxl, g_wxl);
    cudaGetSymbolAddress((void**)&wg1h, g_wg1h); cudaGetSymbolAddress((void**)&wg1l, g_wg1l);
    cudaGetSymbolAddress((void**)&wg2h, g_wg2h); cudaGetSymbolAddress((void**)&wg2l, g_wg2l);
    cudaGetSymbolAddress((void**)&wah, g_wah);   cudaGetSymbolAddress((void**)&wal, g_wal);
    cudaGetSymbolAddress((void**)&w3h, g_w3h);   cudaGetSymbolAddress((void**)&w3l, g_w3l);
    cudaGetSymbolAddress((void**)&wbh, g_wbh);   cudaGetSymbolAddress((void**)&wbl, g_wbl);
    cudaGetSymbolAddress((void**)&w1h, g_w1h);   cudaGetSymbolAddress((void**)&w1l, g_w1l);
    cudaGetSymbolAddress((void**)&w2h, g_w2h);   cudaGetSymbolAddress((void**)&w2l, g_w2l);
    cudaGetSymbolAddress((void**)&perm, g_perm); cudaGetSymbolAddress((void**)&off, g_off);

    const int SMEMP = 81920;
    cudaFuncSetAttribute((const void*)mma_gemm<0,0,0,0,0,1,1,1>, cudaFuncAttributeMaxDynamicSharedMemorySize, SMEMP);
    cudaFuncSetAttribute((const void*)mma_gemm<0,0,0,1,0,1,1,1>, cudaFuncAttributeMaxDynamicSharedMemorySize, SMEMP);
    cudaFuncSetAttribute((const void*)mma_gemm<0,0,0,0,1,0,1,1>, cudaFuncAttributeMaxDynamicSharedMemorySize, SMEMP);
    cudaFuncSetAttribute((const void*)mma_gemm<1,1,1,1,0,1,1,1>, cudaFuncAttributeMaxDynamicSharedMemorySize, SMEMP);
    cudaFuncSetAttribute((const void*)mma_gemm<0,1,1,1,0,1,1,1>, cudaFuncAttributeMaxDynamicSharedMemorySize, SMEMP);
    cudaFuncSetAttribute((const void*)mma_gemm<2,1,1,1,0,1,1,1>, cudaFuncAttributeMaxDynamicSharedMemorySize, SMEMP);
    cudaFuncSetAttribute((const void*)mma_gemm<0,1,1,1,1,1,1,1>, cudaFuncAttributeMaxDynamicSharedMemorySize, SMEMP);
    cudaFuncSetAttribute((const void*)mma_gemm<0,0,1,0,1,0,0,1>, cudaFuncAttributeMaxDynamicSharedMemorySize, SMEMP);
    cudaFuncSetAttribute((const void*)mma_gemm<0,0,0,1,1,0,1,0>, cudaFuncAttributeMaxDynamicSharedMemorySize, SMEMP);

    // launch order arranged so ncu (-s 5 -c 1) profiles launch #6 = backbone L0 mma_gemm
    k_reset<<<MMAX / 256, 256>>>();                                                      // 1
    k_pe<<<(NTOK * 40 + 255) / 256, 256>>>(x);                                           // 2
    k_wt<<<dim3(3, 8, 1),  dim3(32, 8)>>>(w_xyz, wxh, wxl, 75, 256, 96, 19200, 24576);   // 3
    k_wt<<<dim3(8, 8, 1),  dim3(32, 8)>>>(wg1, wg1h, wg1l, 256, 256, 256, 65536, 65536); // 4
    k_wt<<<dim3(8, 8, 1),  dim3(32, 8)>>>(wg2, wg2h, wg2l, 256, 256, 256, 65536, 65536); // 5

    // backbone (bf16x3; argmax protected by margin-gated exact recompute)
    dim3 gT(NTOK / 128, 2);
    mma_gemm<0,0,0,0,0,1,1,1><<<gT, 256, SMEMP>>>(peh, pel, nullptr, nullptr, wxh, wxl, b_xyz,
        nullptr, h0h, h0l, 96, 96, 3, 256, 0, 0, nullptr, nullptr);                      // 6 <- profiled
    mma_gemm<0,0,0,1,0,1,1,1><<<gT, 256, SMEMP>>>(h0h, h0l, nullptr, nullptr, wg1h, wg1l, bg1,
        nullptr, p1h, p1l, 256, 256, 8, 256, 0, 0, nullptr, nullptr);
    mma_gemm<0,0,0,0,1,0,1,1><<<gT, 256, SMEMP>>>(p1h, p1l, nullptr, nullptr, wg2h, wg2l, bg2,
        b2f, nullptr, nullptr, 256, 256, 8, 256, 0, 0, nullptr, nullptr);

    // routing
    k_gate<<<NTOK / 8, 256>>>(ln_g, ln_b, wg);
    k_exact<<<256, 256>>>(x, w_xyz, b_xyz, wg1, bg1, wg2, bg2, ln_g, ln_b, wg);

    // expert weight transposes (only needed before expert chain)
    k_wt<<<dim3(8, 8, 24), dim3(32, 8)>>>(eW_a, wah, wal, 256, 256, 256, 65536, 65536);
    k_wt<<<dim3(16, 8, 8), dim3(32, 8)>>>(eW3, w3h, w3l, 512, 256, 512, 131072, 131072);
    k_wt<<<dim3(8, 8, 24), dim3(32, 8)>>>(eW_b, wbh, wbl, 256, 256, 256, 65536, 65536);
    k_wt<<<dim3(8, 8, 1),  dim3(32, 8)>>>(w1, w1h, w1l, 256, 256, 256, 65536, 65536);
    k_wt<<<dim3(12, 4, 1), dim3(32, 8)>>>(w2, w2h, w2l, 331, 128, 384, 42368, 49152);

    k_hist<<<512, 256>>>();
    k_scan<<<1, 32>>>(cap);
    k_loc<<<512, 32>>>(cap);

    // expert chain
    dim3 gS(MMAX / 128, 2);
    mma_gemm<1,1,1,1,0,1,1,1><<<gS, 256, SMEMP>>>(h0h, h0l, nullptr, nullptr, wah, wal, eb_a,
        nullptr, p1h, p1l, 256, 256, 8, 256, 196608, 768, perm, off);
    mma_gemm<0,1,1,1,0,1,1,1><<<gS, 256, SMEMP>>>(p1h, p1l, nullptr, nullptr, wah + 65536, wal + 65536, eb_a + 256,
        nullptr, p2h, p2l, 256, 256, 8, 256, 196608, 768, perm, off);
    mma_gemm<0,1,1,1,0,1,1,1><<<gS, 256, SMEMP>>>(p2h, p2l, nullptr, nullptr, wah + 131072, wal + 131072, eb_a + 512,
        nullptr, p1h, p1l, 256, 256, 8, 256, 196608, 768, perm, off);
    mma_gemm<2,1,1,1,0,1,1,1><<<gS, 256, SMEMP>>>(h0h, h0l, p1h, p1l, w3h, w3l, eb3,
        nullptr, p2h, p2l, 256, 512, 16, 256, 131072, 256, perm, off);
    mma_gemm<0,1,1,1,0,1,1,1><<<gS, 256, SMEMP>>>(p2h, p2l, nullptr, nullptr, wbh, wbl, eb_b,
        nullptr, p1h, p1l, 256, 256, 8, 256, 196608, 768, perm, off);
    mma_gemm<0,1,1,1,0,1,1,1><<<gS, 256, SMEMP>>>(p1h, p1l, nullptr, nullptr, wbh + 65536, wbl + 65536, eb_b + 256,
        nullptr, p2h, p2l, 256, 256, 8, 256, 196608, 768, perm, off);
    mma_gemm<0,1,1,1,1,1,1,1><<<gS, 256, SMEMP>>>(p2h, p2l, nullptr, nullptr, wbh + 131072, wbl + 131072, eb_b + 512,
        b2f, p1h, p1l, 256, 256, 8, 256, 196608, 768, perm, off);
    mma_gemm<0,0,1,0,1,0,0,1><<<gS, 256, SMEMP>>>(p1h, p1l, nullptr, nullptr, w1h, w1l, nullptr,
        b1f, nullptr, nullptr, 256, 256, 8, 256, 0, 0, perm, off);

    // heads (w2: 2-MMA variant, B effectively bf16 — rgb path only)
    k_cat<<<NTOK, 128>>>(x, emb_a, b1);
    mma_gemm<0,0,0,1,1,0,1,0><<<dim3(NTOK / 128, 1), 256, SMEMP>>>(cath, catl, nullptr, nullptr, w2h, w2l, b2,
        z, nullptr, nullptr, 384, 384, 12, 128, 0, 0, perm, off);
    k_final<<<NTOK / 8, 256>>>(wc, bc, ws, bs, out);
}